// round 3
// baseline (speedup 1.0000x reference)
#include <cuda_runtime.h>
#include <math.h>
#include <stdint.h>

// Problem constants
#define T_ROWS   8192            // B*N
#define C_DIM    1024
#define H_DIM    16
#define D_DIM    64
#define FUSED_N  7168            // 3C + MLP
#define SE_N     2048
#define MLP_DIM  4096
#define INNER    2730
#define INNER_P  2752            // padded K (mult of 32)
#define VG_P     5504            // padded 2*INNER (mult of 128)

// ---------------- scratch (static device allocations) ----------------
__device__ float g_se   [T_ROWS * SE_N];
__device__ float g_xn   [T_ROWS * C_DIM];
__device__ float g_fused[(size_t)T_ROWS * FUSED_N];
__device__ float g_o    [T_ROWS * C_DIM];
__device__ float g_vg   [(size_t)T_ROWS * VG_P];
__device__ float g_h2   [(size_t)T_ROWS * INNER_P];
__device__ float g_mlps [(size_t)T_ROWS * MLP_DIM];
__device__ float g_f    [T_ROWS * C_DIM];
__device__ float g_gate [T_ROWS * H_DIM];
__device__ float g_rms  [4 * H_DIM];
__device__ float g_x2   [T_ROWS * C_DIM];
// tf32-converted (and padded) operands
__device__ float g_embt [T_ROWS * C_DIM];
__device__ float g_Wembt[C_DIM * SE_N];
__device__ float g_Wft  [(size_t)C_DIM * FUSED_N];
__device__ float g_Wmint[(size_t)C_DIM * VG_P];
__device__ float g_bmin [VG_P];
__device__ float g_Wmot [INNER_P * C_DIM];
__device__ float g_Waot [C_DIM * C_DIM];
__device__ float g_Wmo2t[MLP_DIM * C_DIM];

__device__ __forceinline__ float to_tf32(float x)
{
    uint32_t u;
    asm("cvt.rna.tf32.f32 %0, %1;" : "=r"(u) : "f"(x));
    return __uint_as_float(u);
}

// ---------------- convert + pad to tf32 ----------------
__global__ void __launch_bounds__(256) k_cvt(
    const float* __restrict__ in, float* __restrict__ out,
    int rows_in, int cols_in, int cols_out)
{
    const int r = blockIdx.y;
    const int c = blockIdx.x * 256 + threadIdx.x;
    if (c >= cols_out) return;
    float v = (c < cols_in && r < rows_in) ? in[(size_t)r * cols_in + c] : 0.f;
    out[(size_t)r * cols_out + c] = to_tf32(v);
}

// ---------------- tf32 tensor-core GEMM, 128x128x32, 3-stage cp.async ------
#define BM 128
#define BN 128
#define BK 32
#define NSTG 3
#define ASTR 36
#define BSTR 136
#define GSMEM ((NSTG*BM*ASTR + NSTG*BK*BSTR) * (int)sizeof(float))

template<bool RESID>
__global__ void __launch_bounds__(256) tgemm(
    const float* __restrict__ A, int lda,
    const float* __restrict__ B, int ldb,
    const float* __restrict__ bias,
    const float* __restrict__ R, int ldr,
    float* __restrict__ C, int ldc,
    int K)
{
    extern __shared__ float sh[];
    float* As = sh;
    float* Bs = sh + NSTG * BM * ASTR;

    const int tid  = threadIdx.x;
    const int warp = tid >> 5, lane = tid & 31;
    const int wm = warp & 1, wn = warp >> 1;
    const int lr = lane >> 2, lc = lane & 3;
    const int bx = blockIdx.x, by = blockIdx.y;

    const int arow = tid >> 3;
    const int acol = (tid & 7) * 4;
    const int brow = tid >> 5;
    const int bcol = (tid & 31) * 4;

    const float* Ag = A + (size_t)(by * BM + arow) * lda + acol;
    const float* Bg = B + (size_t)brow * ldb + bx * BN + bcol;

    auto load_tile = [&](int stg, int k0) {
        float* Asd = As + stg * BM * ASTR;
        float* Bsd = Bs + stg * BK * BSTR;
#pragma unroll
        for (int i = 0; i < 4; i++) {
            uint32_t dst = (uint32_t)__cvta_generic_to_shared(
                Asd + (arow + i * 32) * ASTR + acol);
            const float* src = Ag + (size_t)(i * 32) * lda + k0;
            asm volatile("cp.async.cg.shared.global [%0], [%1], 16;\n"
                         :: "r"(dst), "l"(src));
        }
#pragma unroll
        for (int i = 0; i < 4; i++) {
            uint32_t dst = (uint32_t)__cvta_generic_to_shared(
                Bsd + (brow + i * 8) * BSTR + bcol);
            const float* src = Bg + (size_t)(k0 + i * 8) * ldb;
            asm volatile("cp.async.cg.shared.global [%0], [%1], 16;\n"
                         :: "r"(dst), "l"(src));
        }
        asm volatile("cp.async.commit_group;\n");
    };

    float acc[4][4][4];
#pragma unroll
    for (int mt = 0; mt < 4; mt++)
#pragma unroll
        for (int nt = 0; nt < 4; nt++)
#pragma unroll
            for (int i = 0; i < 4; i++) acc[mt][nt][i] = 0.f;

    const int ntiles = K / BK;
    load_tile(0, 0);
    load_tile(1, BK);
    asm volatile("cp.async.wait_group 1;\n");
    __syncthreads();

    for (int kt = 0; kt < ntiles; kt++) {
        const int stg = kt % NSTG;
        if (kt + 2 < ntiles) load_tile((kt + 2) % NSTG, (kt + 2) * BK);

        const float* Asd = As + stg * BM * ASTR + (wm * 64 + lr) * ASTR;
        const float* Bsd = Bs + stg * BK * BSTR + wn * 32 + lr;

#pragma unroll
        for (int kf = 0; kf < 4; kf++) {
            uint32_t af[4][4], bf[4][2];
#pragma unroll
            for (int mt = 0; mt < 4; mt++) {
                const float* p = Asd + mt * 16 * ASTR + kf * 8 + lc;
                af[mt][0] = __float_as_uint(p[0]);
                af[mt][1] = __float_as_uint(p[8 * ASTR]);
                af[mt][2] = __float_as_uint(p[4]);
                af[mt][3] = __float_as_uint(p[8 * ASTR + 4]);
            }
#pragma unroll
            for (int nt = 0; nt < 4; nt++) {
                const float* p = Bsd + (kf * 8 + lc) * BSTR + nt * 8;
                bf[nt][0] = __float_as_uint(p[0]);
                bf[nt][1] = __float_as_uint(p[4 * BSTR]);
            }
#pragma unroll
            for (int mt = 0; mt < 4; mt++)
#pragma unroll
                for (int nt = 0; nt < 4; nt++)
                    asm volatile(
                        "mma.sync.aligned.m16n8k8.row.col.f32.tf32.tf32.f32 "
                        "{%0,%1,%2,%3}, {%4,%5,%6,%7}, {%8,%9}, {%0,%1,%2,%3};\n"
                        : "+f"(acc[mt][nt][0]), "+f"(acc[mt][nt][1]),
                          "+f"(acc[mt][nt][2]), "+f"(acc[mt][nt][3])
                        : "r"(af[mt][0]), "r"(af[mt][1]),
                          "r"(af[mt][2]), "r"(af[mt][3]),
                          "r"(bf[nt][0]), "r"(bf[nt][1]));
        }
        if (kt + 1 < ntiles) {
            asm volatile("cp.async.wait_group 1;\n");
            __syncthreads();
        }
    }

#pragma unroll
    for (int mt = 0; mt < 4; mt++) {
        const int gm = by * BM + wm * 64 + mt * 16 + lr;
#pragma unroll
        for (int nt = 0; nt < 4; nt++) {
            const int gn = bx * BN + wn * 32 + nt * 8 + lc * 2;
            const float b0 = bias[gn], b1 = bias[gn + 1];
            float2 v0 = make_float2(acc[mt][nt][0] + b0, acc[mt][nt][1] + b1);
            float2 v1 = make_float2(acc[mt][nt][2] + b0, acc[mt][nt][3] + b1);
            if (RESID) {
                float2 r0 = *(const float2*)(R + (size_t)gm * ldr + gn);
                float2 r1 = *(const float2*)(R + (size_t)(gm + 8) * ldr + gn);
                v0.x += r0.x; v0.y += r0.y;
                v1.x += r1.x; v1.y += r1.y;
            }
            *(float2*)(C + (size_t)gm * ldc + gn) = v0;
            *(float2*)(C + (size_t)(gm + 8) * ldc + gn) = v1;
        }
    }
}

// ---------------- block reduce helper ----------------
__device__ __forceinline__ float block_reduce_sum(float v)
{
    __shared__ float shr[32];
    const int lane = threadIdx.x & 31, wid = threadIdx.x >> 5;
#pragma unroll
    for (int o = 16; o > 0; o >>= 1) v += __shfl_xor_sync(0xffffffffu, v, o);
    __syncthreads();
    if (lane == 0) shr[wid] = v;
    __syncthreads();
    const int nw = blockDim.x >> 5;
    float r = (threadIdx.x < nw) ? shr[threadIdx.x] : 0.f;
    if (wid == 0) {
#pragma unroll
        for (int o = 16; o > 0; o >>= 1) r += __shfl_xor_sync(0xffffffffu, r, o);
        if (lane == 0) shr[0] = r;
    }
    __syncthreads();
    return shr[0];
}

// ---------------- LN(x)*(1+scale)+shift (tf32-rounded output) --------------
__global__ void __launch_bounds__(256) k_lnmod(
    const float* __restrict__ x, const float* __restrict__ lnw,
    const float* __restrict__ lnb, const float* __restrict__ se,
    float* __restrict__ xn)
{
    const int r = blockIdx.x, tid = threadIdx.x;
    const float4 v = ((const float4*)(x + (size_t)r * C_DIM))[tid];
    float s = v.x + v.y + v.z + v.w;
    s = block_reduce_sum(s);
    const float mu = s * (1.f / 1024.f);
    const float dx0 = v.x - mu, dx1 = v.y - mu, dx2 = v.z - mu, dx3 = v.w - mu;
    float q = dx0 * dx0 + dx1 * dx1 + dx2 * dx2 + dx3 * dx3;
    q = block_reduce_sum(q);
    const float rstd = rsqrtf(q * (1.f / 1024.f) + 1e-5f);
    const float4 w = ((const float4*)lnw)[tid];
    const float4 bb = ((const float4*)lnb)[tid];
    const float4 sc = ((const float4*)(se + (size_t)r * SE_N))[tid];
    const float4 sf = ((const float4*)(se + (size_t)r * SE_N + C_DIM))[tid];
    float4 out;
    out.x = to_tf32((dx0 * rstd * w.x + bb.x) * (1.f + sc.x) + sf.x);
    out.y = to_tf32((dx1 * rstd * w.y + bb.y) * (1.f + sc.y) + sf.y);
    out.z = to_tf32((dx2 * rstd * w.z + bb.z) * (1.f + sc.z) + sf.z);
    out.w = to_tf32((dx3 * rstd * w.w + bb.w) * (1.f + sc.w) + sf.w);
    ((float4*)(xn + (size_t)r * C_DIM))[tid] = out;
}

// ---------------- per-head LN of q,k (in place, tf32-rounded) --------------
__global__ void __launch_bounds__(256) k_qkln(
    float* __restrict__ fused,
    const float* __restrict__ qw, const float* __restrict__ qb,
    const float* __restrict__ kw, const float* __restrict__ kb)
{
    const int w = threadIdx.x >> 5, lane = threadIdx.x & 31;
    const int idx = blockIdx.x * 8 + w;
    const int r = idx >> 4, h = idx & 15;
    float* base = fused + (size_t)r * FUSED_N + h * D_DIM;
#pragma unroll
    for (int part = 0; part < 2; part++) {
        float* p = base + part * C_DIM;
        float v0 = p[lane], v1 = p[lane + 32];
        float s = v0 + v1;
#pragma unroll
        for (int o = 16; o > 0; o >>= 1) s += __shfl_xor_sync(0xffffffffu, s, o);
        const float mu = s * (1.f / 64.f);
        const float d0 = v0 - mu, d1 = v1 - mu;
        float q = d0 * d0 + d1 * d1;
#pragma unroll
        for (int o = 16; o > 0; o >>= 1) q += __shfl_xor_sync(0xffffffffu, q, o);
        const float rstd = rsqrtf(q * (1.f / 64.f) + 1e-5f);
        const float* ww = part ? kw : qw;
        const float* bb = part ? kb : qb;
        p[lane]      = to_tf32(d0 * rstd * ww[lane]      + bb[lane]);
        p[lane + 32] = to_tf32(d1 * rstd * ww[lane + 32] + bb[lane + 32]);
    }
}

// ---------------- tensor-core flash attention (tf32 mma) ----------------
// 128 threads, 64 q rows per block (16 per warp), 64-wide kv tiles,
// double-buffered K/V via cp.async.
#define QSTR 68
#define KSTR 68
#define VSTR 72
#define PSTR 72
#define ATT_SMEM ((64*QSTR + 2*64*KSTR + 2*64*VSTR + 64*PSTR) * (int)sizeof(float))

__global__ void __launch_bounds__(128) k_attn_tc(
    const float* __restrict__ fused, float* __restrict__ o)
{
    extern __shared__ float sh[];
    float* Qs = sh;                        // [64][QSTR]
    float* Ks = Qs + 64 * QSTR;            // [2][64][KSTR]
    float* Vs = Ks + 2 * 64 * KSTR;        // [2][64][VSTR]
    float* Ps = Vs + 2 * 64 * VSTR;        // [64][PSTR]

    const int qt = blockIdx.x, bh = blockIdx.y;
    const int b = bh >> 4, h = bh & 15;
    const int tid = threadIdx.x;
    const int warp = tid >> 5, lane = tid & 31;
    const int lr = lane >> 2, lc = lane & 3;

    // Q tile (already tf32 from k_qkln); fold in 1/sqrt(D)
    const float* qbase = fused + (size_t)(b * 2048 + qt * 64) * FUSED_N + h * D_DIM;
    for (int it = tid; it < 1024; it += 128) {
        const int r = it >> 4, c = (it & 15) * 4;
        float4 v = *(const float4*)(qbase + (size_t)r * FUSED_N + c);
        Qs[r * QSTR + c + 0] = v.x * 0.125f;
        Qs[r * QSTR + c + 1] = v.y * 0.125f;
        Qs[r * QSTR + c + 2] = v.z * 0.125f;
        Qs[r * QSTR + c + 3] = v.w * 0.125f;
    }

    auto load_kv = [&](int s, int kt) {
        const float* kb = fused + (size_t)(b * 2048 + kt * 64) * FUSED_N + C_DIM + h * D_DIM;
        const float* vb = kb + C_DIM;
        float* Kd = Ks + s * 64 * KSTR;
        float* Vd = Vs + s * 64 * VSTR;
        for (int it = tid; it < 1024; it += 128) {
            const int r = it >> 4, c = (it & 15) * 4;
            uint32_t dk = (uint32_t)__cvta_generic_to_shared(Kd + r * KSTR + c);
            asm volatile("cp.async.cg.shared.global [%0], [%1], 16;\n"
                         :: "r"(dk), "l"(kb + (size_t)r * FUSED_N + c));
            uint32_t dv = (uint32_t)__cvta_generic_to_shared(Vd + r * VSTR + c);
            asm volatile("cp.async.cg.shared.global [%0], [%1], 16;\n"
                         :: "r"(dv), "l"(vb + (size_t)r * FUSED_N + c));
        }
        asm volatile("cp.async.commit_group;\n");
    };

    float m0 = -1e30f, m1 = -1e30f, l0 = 0.f, l1 = 0.f;
    float oa[8][4];
#pragma unroll
    for (int dt = 0; dt < 8; dt++)
#pragma unroll
        for (int i = 0; i < 4; i++) oa[dt][i] = 0.f;

    load_kv(0, 0);

    const float* Qw = Qs + (warp * 16 + lr) * QSTR;
    float* Pw = Ps + (warp * 16 + lr) * PSTR;

    for (int kt = 0; kt < 32; kt++) {
        const int s = kt & 1;
        asm volatile("cp.async.wait_group 0;\n");
        __syncthreads();
        if (kt + 1 < 32) load_kv(1 - s, kt + 1);

        float* Vd = Vs + s * 64 * VSTR;
        const float* Kd = Ks + s * 64 * KSTR;
        // V -> tf32 in place
        for (int it = tid; it < 4096; it += 128) {
            const int r = it >> 6, c = it & 63;
            Vd[r * VSTR + c] = to_tf32(Vd[r * VSTR + c]);
        }
        __syncthreads();

        // S = Q @ K^T  (16 rows x 64 cols per warp)
        float acc[8][4];
#pragma unroll
        for (int nt = 0; nt < 8; nt++)
#pragma unroll
            for (int i = 0; i < 4; i++) acc[nt][i] = 0.f;

#pragma unroll
        for (int kf = 0; kf < 8; kf++) {
            const uint32_t a0 = __float_as_uint(Qw[kf * 8 + lc]);
            const uint32_t a1 = __float_as_uint(Qw[8 * QSTR + kf * 8 + lc]);
            const uint32_t a2 = __float_as_uint(Qw[kf * 8 + lc + 4]);
            const uint32_t a3 = __float_as_uint(Qw[8 * QSTR + kf * 8 + lc + 4]);
#pragma unroll
            for (int nt = 0; nt < 8; nt++) {
                const float* kp = Kd + (nt * 8 + lr) * KSTR + kf * 8 + lc;
                const uint32_t b0 = __float_as_uint(kp[0]);
                const uint32_t b1 = __float_as_uint(kp[4]);
                asm volatile(
                    "mma.sync.aligned.m16n8k8.row.col.f32.tf32.tf32.f32 "
                    "{%0,%1,%2,%3}, {%4,%5,%6,%7}, {%8,%9}, {%0,%1,%2,%3};\n"
                    : "+f"(acc[nt][0]), "+f"(acc[nt][1]),
                      "+f"(acc[nt][2]), "+f"(acc[nt][3])
                    : "r"(a0), "r"(a1), "r"(a2), "r"(a3), "r"(b0), "r"(b1));
            }
        }

        // online softmax (rows lr and lr+8 of this warp's 16)
        float mx0 = -1e30f, mx1 = -1e30f;
#pragma unroll
        for (int nt = 0; nt < 8; nt++) {
            mx0 = fmaxf(mx0, fmaxf(acc[nt][0], acc[nt][1]));
            mx1 = fmaxf(mx1, fmaxf(acc[nt][2], acc[nt][3]));
        }
        mx0 = fmaxf(mx0, __shfl_xor_sync(0xffffffffu, mx0, 1));
        mx0 = fmaxf(mx0, __shfl_xor_sync(0xffffffffu, mx0, 2));
        mx1 = fmaxf(mx1, __shfl_xor_sync(0xffffffffu, mx1, 1));
        mx1 = fmaxf(mx1, __shfl_xor_sync(0xffffffffu, mx1, 2));
        const float mn0 = fmaxf(m0, mx0), mn1 = fmaxf(m1, mx1);
        const float al0 = __expf(m0 - mn0), al1 = __expf(m1 - mn1);
        m0 = mn0; m1 = mn1;
        float rs0 = 0.f, rs1 = 0.f;
#pragma unroll
        for (int nt = 0; nt < 8; nt++) {
            acc[nt][0] = __expf(acc[nt][0] - mn0);
            acc[nt][1] = __expf(acc[nt][1] - mn0);
            acc[nt][2] = __expf(acc[nt][2] - mn1);
            acc[nt][3] = __expf(acc[nt][3] - mn1);
            rs0 += acc[nt][0] + acc[nt][1];
            rs1 += acc[nt][2] + acc[nt][3];
        }
        rs0 += __shfl_xor_sync(0xffffffffu, rs0, 1);
        rs0 += __shfl_xor_sync(0xffffffffu, rs0, 2);
        rs1 += __shfl_xor_sync(0xffffffffu, rs1, 1);
        rs1 += __shfl_xor_sync(0xffffffffu, rs1, 2);
        l0 = l0 * al0 + rs0;
        l1 = l1 * al1 + rs1;
#pragma unroll
        for (int dt = 0; dt < 8; dt++) {
            oa[dt][0] *= al0; oa[dt][1] *= al0;
            oa[dt][2] *= al1; oa[dt][3] *= al1;
        }

        // P -> smem (tf32), per-warp pane; no block sync needed
#pragma unroll
        for (int nt = 0; nt < 8; nt++) {
            *(float2*)&Pw[nt * 8 + 2 * lc] =
                make_float2(to_tf32(acc[nt][0]), to_tf32(acc[nt][1]));
            *(float2*)&Pw[8 * PSTR + nt * 8 + 2 * lc] =
                make_float2(to_tf32(acc[nt][2]), to_tf32(acc[nt][3]));
        }
        __syncwarp();

        // O += P @ V
#pragma unroll
        for (int kf = 0; kf < 8; kf++) {
            const uint32_t a0 = __float_as_uint(Pw[kf * 8 + lc]);
            const uint32_t a1 = __float_as_uint(Pw[8 * PSTR + kf * 8 + lc]);
            const uint32_t a2 = __float_as_uint(Pw[kf * 8 + lc + 4]);
            const uint32_t a3 = __float_as_uint(Pw[8 * PSTR + kf * 8 + lc + 4]);
#pragma unroll
            for (int dt = 0; dt < 8; dt++) {
                const uint32_t b0 = __float_as_uint(Vd[(kf * 8 + lc) * VSTR + dt * 8 + lr]);
                const uint32_t b1 = __float_as_uint(Vd[(kf * 8 + lc + 4) * VSTR + dt * 8 + lr]);
                asm volatile(
                    "mma.sync.aligned.m16n8k8.row.col.f32.tf32.tf32.f32 "
                    "{%0,%1,%2,%3}, {%4,%5,%6,%7}, {%8,%9}, {%0,%1,%2,%3};\n"
                    : "+f"(oa[dt][0]), "+f"(oa[dt][1]),
                      "+f"(oa[dt][2]), "+f"(oa[dt][3])
                    : "r"(a0), "r"(a1), "r"(a2), "r"(a3), "r"(b0), "r"(b1));
            }
        }
    }

    const float i0 = 1.f / l0, i1 = 1.f / l1;
    float* ob = o + (size_t)(b * 2048 + qt * 64 + warp * 16 + lr) * C_DIM + h * D_DIM;
#pragma unroll
    for (int dt = 0; dt < 8; dt++) {
        *(float2*)&ob[dt * 8 + 2 * lc] =
            make_float2(oa[dt][0] * i0, oa[dt][1] * i0);
        *(float2*)&ob[8 * C_DIM + dt * 8 + 2 * lc] =
            make_float2(oa[dt][2] * i1, oa[dt][3] * i1);
    }
}

// ---------------- h2 = silu(g)*vv, zero padded, tf32 ----------------
__global__ void __launch_bounds__(256) k_silu_h2(
    const float* __restrict__ vg, float* __restrict__ h2)
{
    const int r = blockIdx.x;
    const float* vr = vg + (size_t)r * VG_P;
    float* hr = h2 + (size_t)r * INNER_P;
    for (int c = threadIdx.x; c < INNER_P; c += 256) {
        float out = 0.f;
        if (c < INNER) {
            const float vv = vr[c];
            const float g = vr[INNER + c];
            out = to_tf32(vv * g / (1.f + __expf(-g)));
        }
        hr[c] = out;
    }
}

// ---------------- mlps = tf32(silu(mlp_h)) ----------------
__global__ void __launch_bounds__(256) k_silu_mlp(
    const float* __restrict__ fused, float* __restrict__ mlps)
{
    const int r = blockIdx.x;
    const float* src = fused + (size_t)r * FUSED_N + 3 * C_DIM;
    float* dst = mlps + (size_t)r * MLP_DIM;
    for (int c = threadIdx.x; c < MLP_DIM; c += 256) {
        const float g = src[c];
        dst[c] = to_tf32(g / (1.f + __expf(-g)));
    }
}

// ---------------- gate = tanh(x @ W_g + b_g) ----------------
__global__ void __launch_bounds__(256) k_gate(
    const float* __restrict__ x, const float* __restrict__ Wg,
    const float* __restrict__ bg, float* __restrict__ gate)
{
    __shared__ float xs[1024];
    __shared__ float part[16][17];
    const int r = blockIdx.x, tid = threadIdx.x;
    *(float4*)&xs[tid * 4] = ((const float4*)(x + (size_t)r * C_DIM))[tid];
    __syncthreads();
    const int h = tid & 15, seg = tid >> 4;
    float s = 0.f;
#pragma unroll 8
    for (int c = seg * 64; c < seg * 64 + 64; c++) s += xs[c] * Wg[c * 16 + h];
    part[h][seg] = s;
    __syncthreads();
    if (tid < 16) {
        float t = bg[tid];
#pragma unroll
        for (int sg = 0; sg < 16; sg++) t += part[tid][sg];
        gate[(size_t)r * 16 + tid] = tanhf(t);
    }
}

// ---------------- rms[b,h] over (n,d) of f ----------------
__global__ void __launch_bounds__(256) k_rms(const float* __restrict__ f, float* __restrict__ rms)
{
    const int b = blockIdx.x >> 4, h = blockIdx.x & 15;
    float s = 0.f;
    for (int n = threadIdx.x; n < 2048; n += 256) {
        const float4* fp = (const float4*)(f + (size_t)(b * 2048 + n) * C_DIM + h * D_DIM);
#pragma unroll
        for (int d4 = 0; d4 < 16; d4++) {
            const float4 v = fp[d4];
            s += v.x * v.x + v.y * v.y + v.z * v.z + v.w * v.w;
        }
    }
    s = block_reduce_sum(s);
    if (threadIdx.x == 0)
        rms[blockIdx.x] = fmaxf(sqrtf(s * (1.f / 131072.f)), 1e-6f);
}

// ---------------- o = tf32(o + gate * f / rms) ----------------
__global__ void __launch_bounds__(256) k_combine(
    float* __restrict__ o, const float* __restrict__ f,
    const float* __restrict__ gate, const float* __restrict__ rms)
{
    const int r = blockIdx.x, tid = threadIdx.x;
    const int h = tid >> 4;
    const float g = gate[(size_t)r * 16 + h] / rms[(r >> 11) * 16 + h];
    float4* op = (float4*)(o + (size_t)r * C_DIM) + tid;
    const float4 fv = ((const float4*)(f + (size_t)r * C_DIM))[tid];
    float4 ov = *op;
    ov.x = to_tf32(ov.x + g * fv.x);
    ov.y = to_tf32(ov.y + g * fv.y);
    ov.z = to_tf32(ov.z + g * fv.z);
    ov.w = to_tf32(ov.w + g * fv.w);
    *op = ov;
}

// ---------------- launch ----------------
extern "C" void kernel_launch(void* const* d_in, const int* in_sizes, int n_in,
                              void* d_out, int out_size)
{
    const float* x     = (const float*)d_in[0];
    const float* emb   = (const float*)d_in[1];
    const float* W_emb = (const float*)d_in[2];
    const float* b_emb = (const float*)d_in[3];
    const float* ln_w  = (const float*)d_in[4];
    const float* ln_b  = (const float*)d_in[5];
    const float* W_f   = (const float*)d_in[6];
    const float* b_f   = (const float*)d_in[7];
    const float* qn_w  = (const float*)d_in[8];
    const float* qn_b  = (const float*)d_in[9];
    const float* kn_w  = (const float*)d_in[10];
    const float* kn_b  = (const float*)d_in[11];
    const float* W_ao  = (const float*)d_in[12];
    const float* b_ao  = (const float*)d_in[13];
    const float* W_mo  = (const float*)d_in[14];
    const float* b_mo  = (const float*)d_in[15];
    const float* Wm_in = (const float*)d_in[16];
    const float* bm_in = (const float*)d_in[17];
    const float* Wm_out= (const float*)d_in[18];
    const float* bm_out= (const float*)d_in[19];
    const float* W_g   = (const float*)d_in[20];
    const float* b_g   = (const float*)d_in[21];
    float* out = (float*)d_out;

    float *se, *xn, *fused, *o, *vg, *h2, *mlps, *f, *gate, *rms, *x2;
    float *embt, *Wembt, *Wft, *Wmint, *bmin, *Wmot, *Waot, *Wmo2t;
    cudaGetSymbolAddress((void**)&se,    g_se);
    cudaGetSymbolAddress((void**)&xn,    g_xn);
    cudaGetSymbolAddress((void**)&fused, g_fused);
    cudaGetSymbolAddress((void**)&o,     g_o);
    cudaGetSymbolAddress((void**)&vg,    g_vg);
    cudaGetSymbolAddress((void**)&h2,    g_h2);
    cudaGetSymbolAddress((void**)&mlps,  g_mlps);
    cudaGetSymbolAddress((void**)&f,     g_f);
    cudaGetSymbolAddress((void**)&gate,  g_gate);
    cudaGetSymbolAddress((void**)&rms,   g_rms);
    cudaGetSymbolAddress((void**)&x2,    g_x2);
    cudaGetSymbolAddress((void**)&embt,  g_embt);
    cudaGetSymbolAddress((void**)&Wembt, g_Wembt);
    cudaGetSymbolAddress((void**)&Wft,   g_Wft);
    cudaGetSymbolAddress((void**)&Wmint, g_Wmint);
    cudaGetSymbolAddress((void**)&bmin,  g_bmin);
    cudaGetSymbolAddress((void**)&Wmot,  g_Wmot);
    cudaGetSymbolAddress((void**)&Waot,  g_Waot);
    cudaGetSymbolAddress((void**)&Wmo2t, g_Wmo2t);

    cudaFuncSetAttribute(tgemm<false>, cudaFuncAttributeMaxDynamicSharedMemorySize, GSMEM);
    cudaFuncSetAttribute(tgemm<true>,  cudaFuncAttributeMaxDynamicSharedMemorySize, GSMEM);
    cudaFuncSetAttribute(k_attn_tc, cudaFuncAttributeMaxDynamicSharedMemorySize, ATT_SMEM);

    const int MB = T_ROWS / 128;  // 64
    dim3 blk(256);

    // --- tf32 conversions ---
    k_cvt<<<dim3(C_DIM / 256, T_ROWS), blk>>>(emb,    embt,  T_ROWS, C_DIM, C_DIM);
    k_cvt<<<dim3(SE_N / 256, C_DIM), blk>>>(W_emb,  Wembt, C_DIM, SE_N, SE_N);
    k_cvt<<<dim3(FUSED_N / 256, C_DIM), blk>>>(W_f, Wft,   C_DIM, FUSED_N, FUSED_N);
    k_cvt<<<dim3((VG_P + 255) / 256, C_DIM), blk>>>(Wm_in, Wmint, C_DIM, 2 * INNER, VG_P);
    k_cvt<<<dim3((VG_P + 255) / 256, 1), blk>>>(bm_in, bmin, 1, 2 * INNER, VG_P);
    k_cvt<<<dim3(C_DIM / 256, INNER_P), blk>>>(Wm_out, Wmot, INNER, C_DIM, C_DIM);
    k_cvt<<<dim3(C_DIM / 256, C_DIM), blk>>>(W_ao,  Waot,  C_DIM, C_DIM, C_DIM);
    k_cvt<<<dim3(C_DIM / 256, MLP_DIM), blk>>>(W_mo, Wmo2t, MLP_DIM, C_DIM, C_DIM);

    // 1) se = emb @ W_emb + b_emb
    tgemm<false><<<dim3(SE_N / 128, MB), blk, GSMEM>>>(
        embt, C_DIM, Wembt, SE_N, b_emb, nullptr, 0, se, SE_N, C_DIM);

    // 2) xn = LN(x)*(1+scale)+shift
    k_lnmod<<<T_ROWS, blk>>>(x, ln_w, ln_b, se, xn);

    // 3) fused = xn @ W_f + b_f
    tgemm<false><<<dim3(FUSED_N / 128, MB), blk, GSMEM>>>(
        xn, C_DIM, Wft, FUSED_N, b_f, nullptr, 0, fused, FUSED_N, C_DIM);

    // 4) per-head LN of q,k in place
    k_qkln<<<T_ROWS * H_DIM / 8, blk>>>(fused, qn_w, qn_b, kn_w, kn_b);

    // 5) tensor-core flash attention -> o [B,N,H,D]
    k_attn_tc<<<dim3(32, 64), dim3(128), ATT_SMEM>>>(fused, o);

    // 6) vg = qp @ Wm_in + bm_in
    tgemm<false><<<dim3(VG_P / 128, MB), blk, GSMEM>>>(
        fused, FUSED_N, Wmint, VG_P, bmin, nullptr, 0, vg, VG_P, C_DIM);

    // 7) h2 = silu(g)*vv ; mlps = silu(mlp_h)
    k_silu_h2<<<T_ROWS, blk>>>(vg, h2);
    k_silu_mlp<<<T_ROWS, blk>>>(fused, mlps);

    // 8) f = h2 @ Wm_out + bm_out
    tgemm<false><<<dim3(C_DIM / 128, MB), blk, GSMEM>>>(
        h2, INNER_P, Wmot, C_DIM, bm_out, nullptr, 0, f, C_DIM, INNER_P);

    // 9) gate, rms, combine
    k_gate<<<T_ROWS, blk>>>(x, W_g, b_g, gate);
    k_rms<<<4 * H_DIM, blk>>>(f, rms);
    k_combine<<<T_ROWS, blk>>>(o, f, gate, rms);

    // 10) x2 = x + o @ W_ao + b_ao
    tgemm<true><<<dim3(C_DIM / 128, MB), blk, GSMEM>>>(
        o, C_DIM, Waot, C_DIM, b_ao, x, C_DIM, x2, C_DIM, C_DIM);

    // 11) out = x2 + mlps @ W_mo + b_mo
    tgemm<true><<<dim3(C_DIM / 128, MB), blk, GSMEM>>>(
        mlps, MLP_DIM, Wmo2t, C_DIM, b_mo, x2, C_DIM, out, C_DIM, MLP_DIM);
}

// round 4
// speedup vs baseline: 1.5696x; 1.5696x over previous
#include <cuda_runtime.h>
#include <math.h>
#include <stdint.h>

// Problem constants
#define T_ROWS   8192            // B*N
#define C_DIM    1024
#define H_DIM    16
#define D_DIM    64
#define FUSED_N  7168            // 3C + MLP
#define SE_N     2048
#define MLP_DIM  4096
#define INNER    2730
#define INNER_P  2752            // padded K (mult of 32)
#define VG_P     5504            // padded 2*INNER (mult of 128)

// ---------------- scratch (static device allocations) ----------------
__device__ float g_se   [T_ROWS * SE_N];
__device__ float g_xn   [T_ROWS * C_DIM];
__device__ float g_fused[(size_t)T_ROWS * FUSED_N];
__device__ float g_o    [T_ROWS * C_DIM];
__device__ float g_vg   [(size_t)T_ROWS * VG_P];
__device__ float g_h2   [(size_t)T_ROWS * INNER_P];
__device__ float g_mlps [(size_t)T_ROWS * MLP_DIM];
__device__ float g_f    [T_ROWS * C_DIM];
__device__ float g_gate [T_ROWS * H_DIM];
__device__ float g_rms  [4 * H_DIM];
__device__ float g_x2   [T_ROWS * C_DIM];
// tf32-converted (and padded) operands
__device__ float g_embt [T_ROWS * C_DIM];
__device__ float g_Wembt[C_DIM * SE_N];
__device__ float g_Wft  [(size_t)C_DIM * FUSED_N];
__device__ float g_Wmint[(size_t)C_DIM * VG_P];
__device__ float g_bmin [VG_P];
__device__ float g_Wmot [INNER_P * C_DIM];
__device__ float g_Waot [C_DIM * C_DIM];
__device__ float g_Wmo2t[MLP_DIM * C_DIM];

__device__ __forceinline__ float to_tf32(float x)
{
    uint32_t u;
    asm("cvt.rna.tf32.f32 %0, %1;" : "=r"(u) : "f"(x));
    return __uint_as_float(u);
}

// ---------------- convert + pad to tf32 ----------------
__global__ void __launch_bounds__(256) k_cvt(
    const float* __restrict__ in, float* __restrict__ out,
    int rows_in, int cols_in, int cols_out)
{
    const int r = blockIdx.y;
    const int c = blockIdx.x * 256 + threadIdx.x;
    if (c >= cols_out) return;
    float v = (c < cols_in && r < rows_in) ? in[(size_t)r * cols_in + c] : 0.f;
    out[(size_t)r * cols_out + c] = to_tf32(v);
}

// ---------------- tf32 tensor-core GEMM, 128x128x32, 3-stage cp.async ------
#define BM 128
#define BN 128
#define BK 32
#define NSTG 3
#define ASTR 36
#define BSTR 136
#define GSMEM ((NSTG*BM*ASTR + NSTG*BK*BSTR) * (int)sizeof(float))

template<bool RESID, bool TF32OUT>
__global__ void __launch_bounds__(256) tgemm(
    const float* __restrict__ A, int lda,
    const float* __restrict__ B, int ldb,
    const float* __restrict__ bias,
    const float* __restrict__ R, int ldr,
    float* __restrict__ C, int ldc,
    int K)
{
    extern __shared__ float sh[];
    float* As = sh;
    float* Bs = sh + NSTG * BM * ASTR;

    const int tid  = threadIdx.x;
    const int warp = tid >> 5, lane = tid & 31;
    const int wm = warp & 1, wn = warp >> 1;
    const int lr = lane >> 2, lc = lane & 3;
    const int bx = blockIdx.x, by = blockIdx.y;

    const int arow = tid >> 3;
    const int acol = (tid & 7) * 4;
    const int brow = tid >> 5;
    const int bcol = (tid & 31) * 4;

    const float* Ag = A + (size_t)(by * BM + arow) * lda + acol;
    const float* Bg = B + (size_t)brow * ldb + bx * BN + bcol;

    auto load_tile = [&](int stg, int k0) {
        float* Asd = As + stg * BM * ASTR;
        float* Bsd = Bs + stg * BK * BSTR;
#pragma unroll
        for (int i = 0; i < 4; i++) {
            uint32_t dst = (uint32_t)__cvta_generic_to_shared(
                Asd + (arow + i * 32) * ASTR + acol);
            const float* src = Ag + (size_t)(i * 32) * lda + k0;
            asm volatile("cp.async.cg.shared.global [%0], [%1], 16;\n"
                         :: "r"(dst), "l"(src));
        }
#pragma unroll
        for (int i = 0; i < 4; i++) {
            uint32_t dst = (uint32_t)__cvta_generic_to_shared(
                Bsd + (brow + i * 8) * BSTR + bcol);
            const float* src = Bg + (size_t)(k0 + i * 8) * ldb;
            asm volatile("cp.async.cg.shared.global [%0], [%1], 16;\n"
                         :: "r"(dst), "l"(src));
        }
        asm volatile("cp.async.commit_group;\n");
    };

    float acc[4][4][4];
#pragma unroll
    for (int mt = 0; mt < 4; mt++)
#pragma unroll
        for (int nt = 0; nt < 4; nt++)
#pragma unroll
            for (int i = 0; i < 4; i++) acc[mt][nt][i] = 0.f;

    const int ntiles = K / BK;
    load_tile(0, 0);
    load_tile(1, BK);
    asm volatile("cp.async.wait_group 1;\n");
    __syncthreads();

    for (int kt = 0; kt < ntiles; kt++) {
        const int stg = kt % NSTG;
        if (kt + 2 < ntiles) load_tile((kt + 2) % NSTG, (kt + 2) * BK);

        const float* Asd = As + stg * BM * ASTR + (wm * 64 + lr) * ASTR;
        const float* Bsd = Bs + stg * BK * BSTR + wn * 32 + lr;

#pragma unroll
        for (int kf = 0; kf < 4; kf++) {
            uint32_t af[4][4], bf[4][2];
#pragma unroll
            for (int mt = 0; mt < 4; mt++) {
                const float* p = Asd + mt * 16 * ASTR + kf * 8 + lc;
                af[mt][0] = __float_as_uint(p[0]);
                af[mt][1] = __float_as_uint(p[8 * ASTR]);
                af[mt][2] = __float_as_uint(p[4]);
                af[mt][3] = __float_as_uint(p[8 * ASTR + 4]);
            }
#pragma unroll
            for (int nt = 0; nt < 4; nt++) {
                const float* p = Bsd + (kf * 8 + lc) * BSTR + nt * 8;
                bf[nt][0] = __float_as_uint(p[0]);
                bf[nt][1] = __float_as_uint(p[4 * BSTR]);
            }
#pragma unroll
            for (int mt = 0; mt < 4; mt++)
#pragma unroll
                for (int nt = 0; nt < 4; nt++)
                    asm volatile(
                        "mma.sync.aligned.m16n8k8.row.col.f32.tf32.tf32.f32 "
                        "{%0,%1,%2,%3}, {%4,%5,%6,%7}, {%8,%9}, {%0,%1,%2,%3};\n"
                        : "+f"(acc[mt][nt][0]), "+f"(acc[mt][nt][1]),
                          "+f"(acc[mt][nt][2]), "+f"(acc[mt][nt][3])
                        : "r"(af[mt][0]), "r"(af[mt][1]),
                          "r"(af[mt][2]), "r"(af[mt][3]),
                          "r"(bf[nt][0]), "r"(bf[nt][1]));
        }
        if (kt + 1 < ntiles) {
            asm volatile("cp.async.wait_group 1;\n");
            __syncthreads();
        }
    }

#pragma unroll
    for (int mt = 0; mt < 4; mt++) {
        const int gm = by * BM + wm * 64 + mt * 16 + lr;
#pragma unroll
        for (int nt = 0; nt < 4; nt++) {
            const int gn = bx * BN + wn * 32 + nt * 8 + lc * 2;
            const float b0 = bias[gn], b1 = bias[gn + 1];
            float2 v0 = make_float2(acc[mt][nt][0] + b0, acc[mt][nt][1] + b1);
            float2 v1 = make_float2(acc[mt][nt][2] + b0, acc[mt][nt][3] + b1);
            if (RESID) {
                float2 r0 = *(const float2*)(R + (size_t)gm * ldr + gn);
                float2 r1 = *(const float2*)(R + (size_t)(gm + 8) * ldr + gn);
                v0.x += r0.x; v0.y += r0.y;
                v1.x += r1.x; v1.y += r1.y;
            }
            if (TF32OUT) {
                v0.x = to_tf32(v0.x); v0.y = to_tf32(v0.y);
                v1.x = to_tf32(v1.x); v1.y = to_tf32(v1.y);
            }
            *(float2*)(C + (size_t)gm * ldc + gn) = v0;
            *(float2*)(C + (size_t)(gm + 8) * ldc + gn) = v1;
        }
    }
}

// ---------------- block reduce helper ----------------
__device__ __forceinline__ float block_reduce_sum(float v)
{
    __shared__ float shr[32];
    const int lane = threadIdx.x & 31, wid = threadIdx.x >> 5;
#pragma unroll
    for (int o = 16; o > 0; o >>= 1) v += __shfl_xor_sync(0xffffffffu, v, o);
    __syncthreads();
    if (lane == 0) shr[wid] = v;
    __syncthreads();
    const int nw = blockDim.x >> 5;
    float r = (threadIdx.x < nw) ? shr[threadIdx.x] : 0.f;
    if (wid == 0) {
#pragma unroll
        for (int o = 16; o > 0; o >>= 1) r += __shfl_xor_sync(0xffffffffu, r, o);
        if (lane == 0) shr[0] = r;
    }
    __syncthreads();
    return shr[0];
}

// ---------------- LN(x)*(1+scale)+shift (tf32-rounded output) --------------
__global__ void __launch_bounds__(256) k_lnmod(
    const float* __restrict__ x, const float* __restrict__ lnw,
    const float* __restrict__ lnb, const float* __restrict__ se,
    float* __restrict__ xn)
{
    const int r = blockIdx.x, tid = threadIdx.x;
    const float4 v = ((const float4*)(x + (size_t)r * C_DIM))[tid];
    float s = v.x + v.y + v.z + v.w;
    s = block_reduce_sum(s);
    const float mu = s * (1.f / 1024.f);
    const float dx0 = v.x - mu, dx1 = v.y - mu, dx2 = v.z - mu, dx3 = v.w - mu;
    float q = dx0 * dx0 + dx1 * dx1 + dx2 * dx2 + dx3 * dx3;
    q = block_reduce_sum(q);
    const float rstd = rsqrtf(q * (1.f / 1024.f) + 1e-5f);
    const float4 w = ((const float4*)lnw)[tid];
    const float4 bb = ((const float4*)lnb)[tid];
    const float4 sc = ((const float4*)(se + (size_t)r * SE_N))[tid];
    const float4 sf = ((const float4*)(se + (size_t)r * SE_N + C_DIM))[tid];
    float4 out;
    out.x = to_tf32((dx0 * rstd * w.x + bb.x) * (1.f + sc.x) + sf.x);
    out.y = to_tf32((dx1 * rstd * w.y + bb.y) * (1.f + sc.y) + sf.y);
    out.z = to_tf32((dx2 * rstd * w.z + bb.z) * (1.f + sc.z) + sf.z);
    out.w = to_tf32((dx3 * rstd * w.w + bb.w) * (1.f + sc.w) + sf.w);
    ((float4*)(xn + (size_t)r * C_DIM))[tid] = out;
}

// ---------------- per-head LN of q,k (in place, tf32-rounded) --------------
__global__ void __launch_bounds__(256) k_qkln(
    float* __restrict__ fused,
    const float* __restrict__ qw, const float* __restrict__ qb,
    const float* __restrict__ kw, const float* __restrict__ kb)
{
    const int w = threadIdx.x >> 5, lane = threadIdx.x & 31;
    const int idx = blockIdx.x * 8 + w;
    const int r = idx >> 4, h = idx & 15;
    float* base = fused + (size_t)r * FUSED_N + h * D_DIM;
#pragma unroll
    for (int part = 0; part < 2; part++) {
        float* p = base + part * C_DIM;
        float v0 = p[lane], v1 = p[lane + 32];
        float s = v0 + v1;
#pragma unroll
        for (int o = 16; o > 0; o >>= 1) s += __shfl_xor_sync(0xffffffffu, s, o);
        const float mu = s * (1.f / 64.f);
        const float d0 = v0 - mu, d1 = v1 - mu;
        float q = d0 * d0 + d1 * d1;
#pragma unroll
        for (int o = 16; o > 0; o >>= 1) q += __shfl_xor_sync(0xffffffffu, q, o);
        const float rstd = rsqrtf(q * (1.f / 64.f) + 1e-5f);
        const float* ww = part ? kw : qw;
        const float* bb = part ? kb : qb;
        p[lane]      = to_tf32(d0 * rstd * ww[lane]      + bb[lane]);
        p[lane + 32] = to_tf32(d1 * rstd * ww[lane + 32] + bb[lane + 32]);
    }
}

// ---------------- tensor-core flash attention (tf32 mma) ----------------
// 256 threads (8 warps), 128 q rows per block (16 per warp),
// 64-wide kv tiles double-buffered via cp.async. V already tf32 at source.
#define QSTR 68
#define KSTR 68
#define VSTR 72
#define PSTR 72
#define ATT_SMEM ((128*QSTR + 2*64*KSTR + 2*64*VSTR + 128*PSTR) * (int)sizeof(float))

__global__ void __launch_bounds__(256) k_attn_tc(
    const float* __restrict__ fused, float* __restrict__ o)
{
    extern __shared__ float sh[];
    float* Qs = sh;                        // [128][QSTR]
    float* Ks = Qs + 128 * QSTR;           // [2][64][KSTR]
    float* Vs = Ks + 2 * 64 * KSTR;        // [2][64][VSTR]
    float* Ps = Vs + 2 * 64 * VSTR;        // [8 warps][16][PSTR]

    const int qt = blockIdx.x, bh = blockIdx.y;
    const int b = bh >> 4, h = bh & 15;
    const int tid = threadIdx.x;
    const int warp = tid >> 5, lane = tid & 31;
    const int lr = lane >> 2, lc = lane & 3;

    // Q tile (tf32 from k_qkln); fold in 1/sqrt(D)
    const float* qbase = fused + (size_t)(b * 2048 + qt * 128) * FUSED_N + h * D_DIM;
    for (int it = tid; it < 2048; it += 256) {
        const int r = it >> 4, c = (it & 15) * 4;
        float4 v = *(const float4*)(qbase + (size_t)r * FUSED_N + c);
        Qs[r * QSTR + c + 0] = v.x * 0.125f;
        Qs[r * QSTR + c + 1] = v.y * 0.125f;
        Qs[r * QSTR + c + 2] = v.z * 0.125f;
        Qs[r * QSTR + c + 3] = v.w * 0.125f;
    }

    auto load_kv = [&](int s, int kt) {
        const float* kb = fused + (size_t)(b * 2048 + kt * 64) * FUSED_N + C_DIM + h * D_DIM;
        const float* vb = kb + C_DIM;
        float* Kd = Ks + s * 64 * KSTR;
        float* Vd = Vs + s * 64 * VSTR;
        for (int it = tid; it < 1024; it += 256) {
            const int r = it >> 4, c = (it & 15) * 4;
            uint32_t dk = (uint32_t)__cvta_generic_to_shared(Kd + r * KSTR + c);
            asm volatile("cp.async.cg.shared.global [%0], [%1], 16;\n"
                         :: "r"(dk), "l"(kb + (size_t)r * FUSED_N + c));
            uint32_t dv = (uint32_t)__cvta_generic_to_shared(Vd + r * VSTR + c);
            asm volatile("cp.async.cg.shared.global [%0], [%1], 16;\n"
                         :: "r"(dv), "l"(vb + (size_t)r * FUSED_N + c));
        }
        asm volatile("cp.async.commit_group;\n");
    };

    float m0 = -1e30f, m1 = -1e30f, l0 = 0.f, l1 = 0.f;
    float oa[8][4];
#pragma unroll
    for (int dt = 0; dt < 8; dt++)
#pragma unroll
        for (int i = 0; i < 4; i++) oa[dt][i] = 0.f;

    load_kv(0, 0);

    const float* Qw = Qs + (warp * 16 + lr) * QSTR;
    float* Pw = Ps + (warp * 16 + lr) * PSTR;

    for (int kt = 0; kt < 32; kt++) {
        const int s = kt & 1;
        asm volatile("cp.async.wait_group 0;\n");
        __syncthreads();
        if (kt + 1 < 32) load_kv(1 - s, kt + 1);

        const float* Kd = Ks + s * 64 * KSTR;
        const float* Vd = Vs + s * 64 * VSTR;

        // S = Q @ K^T  (16 rows x 64 cols per warp)
        float acc[8][4];
#pragma unroll
        for (int nt = 0; nt < 8; nt++)
#pragma unroll
            for (int i = 0; i < 4; i++) acc[nt][i] = 0.f;

#pragma unroll
        for (int kf = 0; kf < 8; kf++) {
            const uint32_t a0 = __float_as_uint(Qw[kf * 8 + lc]);
            const uint32_t a1 = __float_as_uint(Qw[8 * QSTR + kf * 8 + lc]);
            const uint32_t a2 = __float_as_uint(Qw[kf * 8 + lc + 4]);
            const uint32_t a3 = __float_as_uint(Qw[8 * QSTR + kf * 8 + lc + 4]);
#pragma unroll
            for (int nt = 0; nt < 8; nt++) {
                const float* kp = Kd + (nt * 8 + lr) * KSTR + kf * 8 + lc;
                const uint32_t b0 = __float_as_uint(kp[0]);
                const uint32_t b1 = __float_as_uint(kp[4]);
                asm volatile(
                    "mma.sync.aligned.m16n8k8.row.col.f32.tf32.tf32.f32 "
                    "{%0,%1,%2,%3}, {%4,%5,%6,%7}, {%8,%9}, {%0,%1,%2,%3};\n"
                    : "+f"(acc[nt][0]), "+f"(acc[nt][1]),
                      "+f"(acc[nt][2]), "+f"(acc[nt][3])
                    : "r"(a0), "r"(a1), "r"(a2), "r"(a3), "r"(b0), "r"(b1));
            }
        }

        // online softmax (rows lr and lr+8 of this warp's 16)
        float mx0 = -1e30f, mx1 = -1e30f;
#pragma unroll
        for (int nt = 0; nt < 8; nt++) {
            mx0 = fmaxf(mx0, fmaxf(acc[nt][0], acc[nt][1]));
            mx1 = fmaxf(mx1, fmaxf(acc[nt][2], acc[nt][3]));
        }
        mx0 = fmaxf(mx0, __shfl_xor_sync(0xffffffffu, mx0, 1));
        mx0 = fmaxf(mx0, __shfl_xor_sync(0xffffffffu, mx0, 2));
        mx1 = fmaxf(mx1, __shfl_xor_sync(0xffffffffu, mx1, 1));
        mx1 = fmaxf(mx1, __shfl_xor_sync(0xffffffffu, mx1, 2));
        const float mn0 = fmaxf(m0, mx0), mn1 = fmaxf(m1, mx1);
        const float al0 = __expf(m0 - mn0), al1 = __expf(m1 - mn1);
        m0 = mn0; m1 = mn1;
        float rs0 = 0.f, rs1 = 0.f;
#pragma unroll
        for (int nt = 0; nt < 8; nt++) {
            acc[nt][0] = __expf(acc[nt][0] - mn0);
            acc[nt][1] = __expf(acc[nt][1] - mn0);
            acc[nt][2] = __expf(acc[nt][2] - mn1);
            acc[nt][3] = __expf(acc[nt][3] - mn1);
            rs0 += acc[nt][0] + acc[nt][1];
            rs1 += acc[nt][2] + acc[nt][3];
        }
        rs0 += __shfl_xor_sync(0xffffffffu, rs0, 1);
        rs0 += __shfl_xor_sync(0xffffffffu, rs0, 2);
        rs1 += __shfl_xor_sync(0xffffffffu, rs1, 1);
        rs1 += __shfl_xor_sync(0xffffffffu, rs1, 2);
        l0 = l0 * al0 + rs0;
        l1 = l1 * al1 + rs1;
#pragma unroll
        for (int dt = 0; dt < 8; dt++) {
            oa[dt][0] *= al0; oa[dt][1] *= al0;
            oa[dt][2] *= al1; oa[dt][3] *= al1;
        }

        // P -> smem (tf32), per-warp pane; warp-local so __syncwarp only
#pragma unroll
        for (int nt = 0; nt < 8; nt++) {
            *(float2*)&Pw[nt * 8 + 2 * lc] =
                make_float2(to_tf32(acc[nt][0]), to_tf32(acc[nt][1]));
            *(float2*)&Pw[8 * PSTR + nt * 8 + 2 * lc] =
                make_float2(to_tf32(acc[nt][2]), to_tf32(acc[nt][3]));
        }
        __syncwarp();

        // O += P @ V
#pragma unroll
        for (int kf = 0; kf < 8; kf++) {
            const uint32_t a0 = __float_as_uint(Pw[kf * 8 + lc]);
            const uint32_t a1 = __float_as_uint(Pw[8 * PSTR + kf * 8 + lc]);
            const uint32_t a2 = __float_as_uint(Pw[kf * 8 + lc + 4]);
            const uint32_t a3 = __float_as_uint(Pw[8 * PSTR + kf * 8 + lc + 4]);
#pragma unroll
            for (int dt = 0; dt < 8; dt++) {
                const uint32_t b0 = __float_as_uint(Vd[(kf * 8 + lc) * VSTR + dt * 8 + lr]);
                const uint32_t b1 = __float_as_uint(Vd[(kf * 8 + lc + 4) * VSTR + dt * 8 + lr]);
                asm volatile(
                    "mma.sync.aligned.m16n8k8.row.col.f32.tf32.tf32.f32 "
                    "{%0,%1,%2,%3}, {%4,%5,%6,%7}, {%8,%9}, {%0,%1,%2,%3};\n"
                    : "+f"(oa[dt][0]), "+f"(oa[dt][1]),
                      "+f"(oa[dt][2]), "+f"(oa[dt][3])
                    : "r"(a0), "r"(a1), "r"(a2), "r"(a3), "r"(b0), "r"(b1));
            }
        }
    }

    const float i0 = 1.f / l0, i1 = 1.f / l1;
    float* ob = o + (size_t)(b * 2048 + qt * 128 + warp * 16 + lr) * C_DIM + h * D_DIM;
#pragma unroll
    for (int dt = 0; dt < 8; dt++) {
        *(float2*)&ob[dt * 8 + 2 * lc] =
            make_float2(oa[dt][0] * i0, oa[dt][1] * i0);
        *(float2*)&ob[8 * C_DIM + dt * 8 + 2 * lc] =
            make_float2(oa[dt][2] * i1, oa[dt][3] * i1);
    }
}

// ---------------- h2 = silu(g)*vv, zero padded, tf32 ----------------
__global__ void __launch_bounds__(256) k_silu_h2(
    const float* __restrict__ vg, float* __restrict__ h2)
{
    const int r = blockIdx.x;
    const float* vr = vg + (size_t)r * VG_P;
    float* hr = h2 + (size_t)r * INNER_P;
    for (int c = threadIdx.x; c < INNER_P; c += 256) {
        float out = 0.f;
        if (c < INNER) {
            const float vv = vr[c];
            const float g = vr[INNER + c];
            out = to_tf32(vv * g / (1.f + __expf(-g)));
        }
        hr[c] = out;
    }
}

// ---------------- mlps = tf32(silu(mlp_h)) ----------------
__global__ void __launch_bounds__(256) k_silu_mlp(
    const float* __restrict__ fused, float* __restrict__ mlps)
{
    const int r = blockIdx.x;
    const float* src = fused + (size_t)r * FUSED_N + 3 * C_DIM;
    float* dst = mlps + (size_t)r * MLP_DIM;
    for (int c = threadIdx.x; c < MLP_DIM; c += 256) {
        const float g = src[c];
        dst[c] = to_tf32(g / (1.f + __expf(-g)));
    }
}

// ---------------- gate = tanh(x @ W_g + b_g) ----------------
__global__ void __launch_bounds__(256) k_gate(
    const float* __restrict__ x, const float* __restrict__ Wg,
    const float* __restrict__ bg, float* __restrict__ gate)
{
    __shared__ float xs[1024];
    __shared__ float part[16][17];
    const int r = blockIdx.x, tid = threadIdx.x;
    *(float4*)&xs[tid * 4] = ((const float4*)(x + (size_t)r * C_DIM))[tid];
    __syncthreads();
    const int h = tid & 15, seg = tid >> 4;
    float s = 0.f;
#pragma unroll 8
    for (int c = seg * 64; c < seg * 64 + 64; c++) s += xs[c] * Wg[c * 16 + h];
    part[h][seg] = s;
    __syncthreads();
    if (tid < 16) {
        float t = bg[tid];
#pragma unroll
        for (int sg = 0; sg < 16; sg++) t += part[tid][sg];
        gate[(size_t)r * 16 + tid] = tanhf(t);
    }
}

// ---------------- rms[b,h] over (n,d) of f ----------------
__global__ void __launch_bounds__(256) k_rms(const float* __restrict__ f, float* __restrict__ rms)
{
    const int b = blockIdx.x >> 4, h = blockIdx.x & 15;
    float s = 0.f;
    for (int n = threadIdx.x; n < 2048; n += 256) {
        const float4* fp = (const float4*)(f + (size_t)(b * 2048 + n) * C_DIM + h * D_DIM);
#pragma unroll
        for (int d4 = 0; d4 < 16; d4++) {
            const float4 v = fp[d4];
            s += v.x * v.x + v.y * v.y + v.z * v.z + v.w * v.w;
        }
    }
    s = block_reduce_sum(s);
    if (threadIdx.x == 0)
        rms[blockIdx.x] = fmaxf(sqrtf(s * (1.f / 131072.f)), 1e-6f);
}

// ---------------- o = tf32(o + gate * f / rms) ----------------
__global__ void __launch_bounds__(256) k_combine(
    float* __restrict__ o, const float* __restrict__ f,
    const float* __restrict__ gate, const float* __restrict__ rms)
{
    const int r = blockIdx.x, tid = threadIdx.x;
    const int h = tid >> 4;
    const float g = gate[(size_t)r * 16 + h] / rms[(r >> 11) * 16 + h];
    float4* op = (float4*)(o + (size_t)r * C_DIM) + tid;
    const float4 fv = ((const float4*)(f + (size_t)r * C_DIM))[tid];
    float4 ov = *op;
    ov.x = to_tf32(ov.x + g * fv.x);
    ov.y = to_tf32(ov.y + g * fv.y);
    ov.z = to_tf32(ov.z + g * fv.z);
    ov.w = to_tf32(ov.w + g * fv.w);
    *op = ov;
}

// ---------------- launch ----------------
extern "C" void kernel_launch(void* const* d_in, const int* in_sizes, int n_in,
                              void* d_out, int out_size)
{
    const float* x     = (const float*)d_in[0];
    const float* emb   = (const float*)d_in[1];
    const float* W_emb = (const float*)d_in[2];
    const float* b_emb = (const float*)d_in[3];
    const float* ln_w  = (const float*)d_in[4];
    const float* ln_b  = (const float*)d_in[5];
    const float* W_f   = (const float*)d_in[6];
    const float* b_f   = (const float*)d_in[7];
    const float* qn_w  = (const float*)d_in[8];
    const float* qn_b  = (const float*)d_in[9];
    const float* kn_w  = (const float*)d_in[10];
    const float* kn_b  = (const float*)d_in[11];
    const float* W_ao  = (const float*)d_in[12];
    const float* b_ao  = (const float*)d_in[13];
    const float* W_mo  = (const float*)d_in[14];
    const float* b_mo  = (const float*)d_in[15];
    const float* Wm_in = (const float*)d_in[16];
    const float* bm_in = (const float*)d_in[17];
    const float* Wm_out= (const float*)d_in[18];
    const float* bm_out= (const float*)d_in[19];
    const float* W_g   = (const float*)d_in[20];
    const float* b_g   = (const float*)d_in[21];
    float* out = (float*)d_out;

    float *se, *xn, *fused, *o, *vg, *h2, *mlps, *f, *gate, *rms, *x2;
    float *embt, *Wembt, *Wft, *Wmint, *bmin, *Wmot, *Waot, *Wmo2t;
    cudaGetSymbolAddress((void**)&se,    g_se);
    cudaGetSymbolAddress((void**)&xn,    g_xn);
    cudaGetSymbolAddress((void**)&fused, g_fused);
    cudaGetSymbolAddress((void**)&o,     g_o);
    cudaGetSymbolAddress((void**)&vg,    g_vg);
    cudaGetSymbolAddress((void**)&h2,    g_h2);
    cudaGetSymbolAddress((void**)&mlps,  g_mlps);
    cudaGetSymbolAddress((void**)&f,     g_f);
    cudaGetSymbolAddress((void**)&gate,  g_gate);
    cudaGetSymbolAddress((void**)&rms,   g_rms);
    cudaGetSymbolAddress((void**)&x2,    g_x2);
    cudaGetSymbolAddress((void**)&embt,  g_embt);
    cudaGetSymbolAddress((void**)&Wembt, g_Wembt);
    cudaGetSymbolAddress((void**)&Wft,   g_Wft);
    cudaGetSymbolAddress((void**)&Wmint, g_Wmint);
    cudaGetSymbolAddress((void**)&bmin,  g_bmin);
    cudaGetSymbolAddress((void**)&Wmot,  g_Wmot);
    cudaGetSymbolAddress((void**)&Waot,  g_Waot);
    cudaGetSymbolAddress((void**)&Wmo2t, g_Wmo2t);

    cudaFuncSetAttribute(tgemm<false, false>, cudaFuncAttributeMaxDynamicSharedMemorySize, GSMEM);
    cudaFuncSetAttribute(tgemm<false, true>,  cudaFuncAttributeMaxDynamicSharedMemorySize, GSMEM);
    cudaFuncSetAttribute(tgemm<true, false>,  cudaFuncAttributeMaxDynamicSharedMemorySize, GSMEM);
    cudaFuncSetAttribute(k_attn_tc, cudaFuncAttributeMaxDynamicSharedMemorySize, ATT_SMEM);

    const int MB = T_ROWS / 128;  // 64
    dim3 blk(256);

    // --- tf32 conversions ---
    k_cvt<<<dim3(C_DIM / 256, T_ROWS), blk>>>(emb,    embt,  T_ROWS, C_DIM, C_DIM);
    k_cvt<<<dim3(SE_N / 256, C_DIM), blk>>>(W_emb,  Wembt, C_DIM, SE_N, SE_N);
    k_cvt<<<dim3(FUSED_N / 256, C_DIM), blk>>>(W_f, Wft,   C_DIM, FUSED_N, FUSED_N);
    k_cvt<<<dim3((VG_P + 255) / 256, C_DIM), blk>>>(Wm_in, Wmint, C_DIM, 2 * INNER, VG_P);
    k_cvt<<<dim3((VG_P + 255) / 256, 1), blk>>>(bm_in, bmin, 1, 2 * INNER, VG_P);
    k_cvt<<<dim3(C_DIM / 256, INNER_P), blk>>>(Wm_out, Wmot, INNER, C_DIM, C_DIM);
    k_cvt<<<dim3(C_DIM / 256, C_DIM), blk>>>(W_ao,  Waot,  C_DIM, C_DIM, C_DIM);
    k_cvt<<<dim3(C_DIM / 256, MLP_DIM), blk>>>(W_mo, Wmo2t, MLP_DIM, C_DIM, C_DIM);

    // 1) se = emb @ W_emb + b_emb
    tgemm<false, false><<<dim3(SE_N / 128, MB), blk, GSMEM>>>(
        embt, C_DIM, Wembt, SE_N, b_emb, nullptr, 0, se, SE_N, C_DIM);

    // 2) xn = LN(x)*(1+scale)+shift
    k_lnmod<<<T_ROWS, blk>>>(x, ln_w, ln_b, se, xn);

    // 3) fused = xn @ W_f + b_f  (tf32-rounded output: v/mlp_h ready for mma)
    tgemm<false, true><<<dim3(FUSED_N / 128, MB), blk, GSMEM>>>(
        xn, C_DIM, Wft, FUSED_N, b_f, nullptr, 0, fused, FUSED_N, C_DIM);

    // 4) per-head LN of q,k in place
    k_qkln<<<T_ROWS * H_DIM / 8, blk>>>(fused, qn_w, qn_b, kn_w, kn_b);

    // 5) tensor-core flash attention -> o [B,N,H,D]
    k_attn_tc<<<dim3(16, 64), blk, ATT_SMEM>>>(fused, o);

    // 6) vg = qp @ Wm_in + bm_in
    tgemm<false, false><<<dim3(VG_P / 128, MB), blk, GSMEM>>>(
        fused, FUSED_N, Wmint, VG_P, bmin, nullptr, 0, vg, VG_P, C_DIM);

    // 7) h2 = silu(g)*vv ; mlps = silu(mlp_h)
    k_silu_h2<<<T_ROWS, blk>>>(vg, h2);
    k_silu_mlp<<<T_ROWS, blk>>>(fused, mlps);

    // 8) f = h2 @ Wm_out + bm_out
    tgemm<false, false><<<dim3(C_DIM / 128, MB), blk, GSMEM>>>(
        h2, INNER_P, Wmot, C_DIM, bm_out, nullptr, 0, f, C_DIM, INNER_P);

    // 9) gate, rms, combine
    k_gate<<<T_ROWS, blk>>>(x, W_g, b_g, gate);
    k_rms<<<4 * H_DIM, blk>>>(f, rms);
    k_combine<<<T_ROWS, blk>>>(o, f, gate, rms);

    // 10) x2 = x + o @ W_ao + b_ao
    tgemm<true, false><<<dim3(C_DIM / 128, MB), blk, GSMEM>>>(
        o, C_DIM, Waot, C_DIM, b_ao, x, C_DIM, x2, C_DIM, C_DIM);

    // 11) out = x2 + mlps @ W_mo + b_mo
    tgemm<true, false><<<dim3(C_DIM / 128, MB), blk, GSMEM>>>(
        mlps, MLP_DIM, Wmo2t, C_DIM, b_mo, x2, C_DIM, out, C_DIM, MLP_DIM);
}

// round 5
// speedup vs baseline: 2.5764x; 1.6414x over previous
#include <cuda_runtime.h>
#include <cuda_fp16.h>
#include <math.h>
#include <stdint.h>

// Problem constants
#define T_ROWS   8192            // B*N
#define C_DIM    1024
#define H_DIM    16
#define D_DIM    64
#define FUSED_N  7168            // 3C + MLP
#define SE_N     2048
#define MLP_DIM  4096
#define INNER    2730
#define INNER_P  2752            // padded K (mult of 32)
#define VG_P     5504            // padded 2*INNER (mult of 128)

// ---------------- scratch (static device allocations) ----------------
__device__ float  g_se   [T_ROWS * SE_N];
__device__ __half g_xn   [T_ROWS * C_DIM];
__device__ __half g_fused[(size_t)T_ROWS * FUSED_N];
__device__ __half g_o    [T_ROWS * C_DIM];
__device__ __half g_vg   [(size_t)T_ROWS * VG_P];
__device__ __half g_h2   [(size_t)T_ROWS * INNER_P];
__device__ __half g_mlps [(size_t)T_ROWS * MLP_DIM];
__device__ float  g_f    [T_ROWS * C_DIM];
__device__ float  g_gate [T_ROWS * H_DIM];
__device__ float  g_rms  [4 * H_DIM];
__device__ float  g_x2   [T_ROWS * C_DIM];
// half-converted (and padded) operands
__device__ __half g_embt [T_ROWS * C_DIM];
__device__ __half g_Wembt[C_DIM * SE_N];
__device__ __half g_Wft  [(size_t)C_DIM * FUSED_N];
__device__ __half g_Wmint[(size_t)C_DIM * VG_P];
__device__ float  g_bmin [VG_P];
__device__ __half g_Wmot [INNER_P * C_DIM];
__device__ __half g_Waot [C_DIM * C_DIM];
__device__ __half g_Wmo2t[MLP_DIM * C_DIM];

__device__ __forceinline__ uint32_t pack_h2f(float lo, float hi)
{
    uint32_t u;
    asm("cvt.rn.f16x2.f32 %0, %1, %2;" : "=r"(u) : "f"(hi), "f"(lo));
    return u;
}

// ---------------- convert + pad ----------------
__global__ void __launch_bounds__(256) k_cvth(
    const float* __restrict__ in, __half* __restrict__ out,
    int rows_in, int cols_in, int cols_out)
{
    const int r = blockIdx.y;
    const int c = blockIdx.x * 256 + threadIdx.x;
    if (c >= cols_out) return;
    float v = (c < cols_in && r < rows_in) ? in[(size_t)r * cols_in + c] : 0.f;
    out[(size_t)r * cols_out + c] = __float2half(v);
}

__global__ void __launch_bounds__(256) k_padf(
    const float* __restrict__ in, float* __restrict__ out,
    int cols_in, int cols_out)
{
    const int c = blockIdx.x * 256 + threadIdx.x;
    if (c >= cols_out) return;
    out[c] = (c < cols_in) ? in[c] : 0.f;
}

// ---------------- fp16 tensor-core GEMM, 128x128x32, 3-stage cp.async ------
#define BM 128
#define BN 128
#define BK 32
#define NSTG 3
#define AH 40     // BK+8 halves; row = 80B (16B mult), 20-word stride conflict-free
#define BH 136    // BN+8 halves; row = 272B, 68-word stride conflict-free
#define GSMEM ((NSTG*BM*AH + NSTG*BK*BH) * (int)sizeof(__half))

#define MMA_F16(D, A0,A1,A2,A3, B0,B1)                                        \
    asm volatile(                                                             \
        "mma.sync.aligned.m16n8k16.row.col.f32.f16.f16.f32 "                  \
        "{%0,%1,%2,%3}, {%4,%5,%6,%7}, {%8,%9}, {%0,%1,%2,%3};\n"            \
        : "+f"((D)[0]), "+f"((D)[1]), "+f"((D)[2]), "+f"((D)[3])              \
        : "r"(A0), "r"(A1), "r"(A2), "r"(A3), "r"(B0), "r"(B1))

#define LDSM_X4(R0,R1,R2,R3, ADDR)                                            \
    asm volatile("ldmatrix.sync.aligned.m8n8.x4.shared.b16 "                  \
                 "{%0,%1,%2,%3}, [%4];"                                       \
                 : "=r"(R0), "=r"(R1), "=r"(R2), "=r"(R3) : "r"(ADDR))

#define LDSM_X4T(R0,R1,R2,R3, ADDR)                                           \
    asm volatile("ldmatrix.sync.aligned.m8n8.x4.trans.shared.b16 "            \
                 "{%0,%1,%2,%3}, [%4];"                                       \
                 : "=r"(R0), "=r"(R1), "=r"(R2), "=r"(R3) : "r"(ADDR))

template<typename OutT, bool RESID>
__global__ void __launch_bounds__(256) tgemm_h(
    const __half* __restrict__ A, int lda,
    const __half* __restrict__ B, int ldb,
    const float* __restrict__ bias,
    const float* __restrict__ R, int ldr,
    OutT* __restrict__ C, int ldc,
    int K)
{
    extern __shared__ __half sh[];
    __half* As = sh;                       // [NSTG][BM][AH]
    __half* Bs = sh + NSTG * BM * AH;      // [NSTG][BK][BH]

    const int tid  = threadIdx.x;
    const int warp = tid >> 5, lane = tid & 31;
    const int wm = warp & 1, wn = warp >> 1;
    const int lr = lane >> 2, lc = lane & 3;
    const int bx = blockIdx.x, by = blockIdx.y;

    const int arow = tid >> 1;           // 0..127
    const int acol = (tid & 1) * 16;     // 0 or 16 halves
    const int brow = tid >> 3;           // 0..31
    const int bcol = (tid & 7) * 8;      // 0..56 halves

    const __half* Ag = A + (size_t)(by * BM + arow) * lda + acol;
    const __half* Bg = B + (size_t)brow * ldb + bx * BN + bcol;

    auto load_tile = [&](int stg, int k0) {
        __half* Asd = As + stg * BM * AH;
        __half* Bsd = Bs + stg * BK * BH;
        uint32_t d0 = (uint32_t)__cvta_generic_to_shared(Asd + arow * AH + acol);
        asm volatile("cp.async.cg.shared.global [%0], [%1], 16;\n"
                     :: "r"(d0), "l"(Ag + k0));
        asm volatile("cp.async.cg.shared.global [%0], [%1], 16;\n"
                     :: "r"(d0 + 16), "l"(Ag + k0 + 8));
        uint32_t d1 = (uint32_t)__cvta_generic_to_shared(Bsd + brow * BH + bcol);
        asm volatile("cp.async.cg.shared.global [%0], [%1], 16;\n"
                     :: "r"(d1), "l"(Bg + (size_t)k0 * ldb));
        asm volatile("cp.async.cg.shared.global [%0], [%1], 16;\n"
                     :: "r"(d1 + 128), "l"(Bg + (size_t)k0 * ldb + 64));
        asm volatile("cp.async.commit_group;\n");
    };

    float acc[4][4][4];
#pragma unroll
    for (int mt = 0; mt < 4; mt++)
#pragma unroll
        for (int nt = 0; nt < 4; nt++)
#pragma unroll
            for (int i = 0; i < 4; i++) acc[mt][nt][i] = 0.f;

    const int ntiles = K / BK;
    load_tile(0, 0);
    load_tile(1, BK);
    asm volatile("cp.async.wait_group 1;\n");
    __syncthreads();

    for (int kt = 0; kt < ntiles; kt++) {
        const int stg = kt % NSTG;
        if (kt + 2 < ntiles) load_tile((kt + 2) % NSTG, (kt + 2) * BK);

        const __half* Asd = As + stg * BM * AH;
        const __half* Bsd = Bs + stg * BK * BH;

#pragma unroll
        for (int kf = 0; kf < 2; kf++) {
            uint32_t af[4][4];
#pragma unroll
            for (int mt = 0; mt < 4; mt++) {
                uint32_t ad = (uint32_t)__cvta_generic_to_shared(
                    Asd + (wm * 64 + mt * 16 + (lane & 15)) * AH +
                    kf * 16 + (lane >> 4) * 8);
                LDSM_X4(af[mt][0], af[mt][1], af[mt][2], af[mt][3], ad);
            }
            uint32_t bf[4][2];
#pragma unroll
            for (int nb = 0; nb < 2; nb++) {
                uint32_t bd = (uint32_t)__cvta_generic_to_shared(
                    Bsd + (kf * 16 + (lane & 15)) * BH +
                    wn * 32 + nb * 16 + (lane >> 4) * 8);
                LDSM_X4T(bf[2*nb][0], bf[2*nb][1], bf[2*nb+1][0], bf[2*nb+1][1], bd);
            }
#pragma unroll
            for (int mt = 0; mt < 4; mt++)
#pragma unroll
                for (int nt = 0; nt < 4; nt++)
                    MMA_F16(acc[mt][nt], af[mt][0], af[mt][1], af[mt][2], af[mt][3],
                            bf[nt][0], bf[nt][1]);
        }
        if (kt + 1 < ntiles) {
            asm volatile("cp.async.wait_group 1;\n");
            __syncthreads();
        }
    }

#pragma unroll
    for (int mt = 0; mt < 4; mt++) {
        const int gm = by * BM + wm * 64 + mt * 16 + lr;
#pragma unroll
        for (int nt = 0; nt < 4; nt++) {
            const int gn = bx * BN + wn * 32 + nt * 8 + lc * 2;
            const float b0 = bias[gn], b1 = bias[gn + 1];
            float2 v0 = make_float2(acc[mt][nt][0] + b0, acc[mt][nt][1] + b1);
            float2 v1 = make_float2(acc[mt][nt][2] + b0, acc[mt][nt][3] + b1);
            if (RESID) {
                float2 r0 = *(const float2*)(R + (size_t)gm * ldr + gn);
                float2 r1 = *(const float2*)(R + (size_t)(gm + 8) * ldr + gn);
                v0.x += r0.x; v0.y += r0.y;
                v1.x += r1.x; v1.y += r1.y;
            }
            if (sizeof(OutT) == 2) {
                *(uint32_t*)((__half*)C + (size_t)gm * ldc + gn) = pack_h2f(v0.x, v0.y);
                *(uint32_t*)((__half*)C + (size_t)(gm + 8) * ldc + gn) = pack_h2f(v1.x, v1.y);
            } else {
                *(float2*)((float*)C + (size_t)gm * ldc + gn) = v0;
                *(float2*)((float*)C + (size_t)(gm + 8) * ldc + gn) = v1;
            }
        }
    }
}

// ---------------- block reduce helper ----------------
__device__ __forceinline__ float block_reduce_sum(float v)
{
    __shared__ float shr[32];
    const int lane = threadIdx.x & 31, wid = threadIdx.x >> 5;
#pragma unroll
    for (int o = 16; o > 0; o >>= 1) v += __shfl_xor_sync(0xffffffffu, v, o);
    __syncthreads();
    if (lane == 0) shr[wid] = v;
    __syncthreads();
    const int nw = blockDim.x >> 5;
    float r = (threadIdx.x < nw) ? shr[threadIdx.x] : 0.f;
    if (wid == 0) {
#pragma unroll
        for (int o = 16; o > 0; o >>= 1) r += __shfl_xor_sync(0xffffffffu, r, o);
        if (lane == 0) shr[0] = r;
    }
    __syncthreads();
    return shr[0];
}

// ---------------- LN(x)*(1+scale)+shift -> half ----------------
__global__ void __launch_bounds__(256) k_lnmod(
    const float* __restrict__ x, const float* __restrict__ lnw,
    const float* __restrict__ lnb, const float* __restrict__ se,
    __half* __restrict__ xn)
{
    const int r = blockIdx.x, tid = threadIdx.x;
    const float4 v = ((const float4*)(x + (size_t)r * C_DIM))[tid];
    float s = v.x + v.y + v.z + v.w;
    s = block_reduce_sum(s);
    const float mu = s * (1.f / 1024.f);
    const float dx0 = v.x - mu, dx1 = v.y - mu, dx2 = v.z - mu, dx3 = v.w - mu;
    float q = dx0 * dx0 + dx1 * dx1 + dx2 * dx2 + dx3 * dx3;
    q = block_reduce_sum(q);
    const float rstd = rsqrtf(q * (1.f / 1024.f) + 1e-5f);
    const float4 w = ((const float4*)lnw)[tid];
    const float4 bb = ((const float4*)lnb)[tid];
    const float4 sc = ((const float4*)(se + (size_t)r * SE_N))[tid];
    const float4 sf = ((const float4*)(se + (size_t)r * SE_N + C_DIM))[tid];
    const float o0 = (dx0 * rstd * w.x + bb.x) * (1.f + sc.x) + sf.x;
    const float o1 = (dx1 * rstd * w.y + bb.y) * (1.f + sc.y) + sf.y;
    const float o2 = (dx2 * rstd * w.z + bb.z) * (1.f + sc.z) + sf.z;
    const float o3 = (dx3 * rstd * w.w + bb.w) * (1.f + sc.w) + sf.w;
    ((uint2*)(xn + (size_t)r * C_DIM))[tid] =
        make_uint2(pack_h2f(o0, o1), pack_h2f(o2, o3));
}

// ---------------- per-head LN of q,k (in place, half) ----------------
__global__ void __launch_bounds__(256) k_qkln(
    __half* __restrict__ fused,
    const float* __restrict__ qw, const float* __restrict__ qb,
    const float* __restrict__ kw, const float* __restrict__ kb)
{
    const int w = threadIdx.x >> 5, lane = threadIdx.x & 31;
    const int idx = blockIdx.x * 8 + w;
    const int r = idx >> 4, h = idx & 15;
    __half* base = fused + (size_t)r * FUSED_N + h * D_DIM;
#pragma unroll
    for (int part = 0; part < 2; part++) {
        __half* p = base + part * C_DIM;
        float v0 = __half2float(p[lane]), v1 = __half2float(p[lane + 32]);
        float s = v0 + v1;
#pragma unroll
        for (int o = 16; o > 0; o >>= 1) s += __shfl_xor_sync(0xffffffffu, s, o);
        const float mu = s * (1.f / 64.f);
        const float d0 = v0 - mu, d1 = v1 - mu;
        float q = d0 * d0 + d1 * d1;
#pragma unroll
        for (int o = 16; o > 0; o >>= 1) q += __shfl_xor_sync(0xffffffffu, q, o);
        const float rstd = rsqrtf(q * (1.f / 64.f) + 1e-5f);
        const float* ww = part ? kw : qw;
        const float* bb = part ? kb : qb;
        p[lane]      = __float2half(d0 * rstd * ww[lane]      + bb[lane]);
        p[lane + 32] = __float2half(d1 * rstd * ww[lane + 32] + bb[lane + 32]);
    }
}

// ---------------- fp16 tensor-core flash attention ----------------
// 256 threads (8 warps), 128 q rows/block (16 per warp), 64-wide kv tiles,
// double-buffered cp.async. Q frags hoisted to registers; P stays in regs.
#define QH 72
#define KH 72
#define VH 72
#define ATT_SMEM ((128*QH + 2*64*KH + 2*64*VH) * (int)sizeof(__half))

__global__ void __launch_bounds__(256) k_attn_h(
    const __half* __restrict__ fused, __half* __restrict__ o)
{
    extern __shared__ __half shh[];
    __half* Qs = shh;                      // [128][QH]
    __half* Ks = Qs + 128 * QH;            // [2][64][KH]
    __half* Vs = Ks + 2 * 64 * KH;         // [2][64][VH]

    const int qt = blockIdx.x, bh = blockIdx.y;
    const int b = bh >> 4, h = bh & 15;
    const int tid = threadIdx.x;
    const int warp = tid >> 5, lane = tid & 31;
    const int lr = lane >> 2, lc = lane & 3;

    // Q fill (scale by 1/8 — exact in fp16)
    const __half* qbase = fused + (size_t)(b * 2048 + qt * 128) * FUSED_N + h * D_DIM;
    const __half2 scl = __float2half2_rn(0.125f);
    for (int it = tid; it < 4096; it += 256) {
        const int r = it >> 5, c = (it & 31) * 2;
        __half2 v = *(const __half2*)(qbase + (size_t)r * FUSED_N + c);
        *(__half2*)(Qs + r * QH + c) = __hmul2(v, scl);
    }

    auto load_kv = [&](int s, int kt) {
        const __half* kb = fused + (size_t)(b * 2048 + kt * 64) * FUSED_N + C_DIM + h * D_DIM;
        const __half* vb = kb + C_DIM;
        __half* Kd = Ks + s * 64 * KH;
        __half* Vd = Vs + s * 64 * VH;
        for (int it = tid; it < 512; it += 256) {
            const int r = it >> 3, c = (it & 7) * 8;
            uint32_t dk = (uint32_t)__cvta_generic_to_shared(Kd + r * KH + c);
            asm volatile("cp.async.cg.shared.global [%0], [%1], 16;\n"
                         :: "r"(dk), "l"(kb + (size_t)r * FUSED_N + c));
            uint32_t dv = (uint32_t)__cvta_generic_to_shared(Vd + r * VH + c);
            asm volatile("cp.async.cg.shared.global [%0], [%1], 16;\n"
                         :: "r"(dv), "l"(vb + (size_t)r * FUSED_N + c));
        }
        asm volatile("cp.async.commit_group;\n");
    };

    load_kv(0, 0);
    asm volatile("cp.async.wait_group 0;\n");
    __syncthreads();

    // hoist Q fragments (4 k-chunks of 16)
    uint32_t qa[4][4];
#pragma unroll
    for (int kf = 0; kf < 4; kf++) {
        uint32_t ad = (uint32_t)__cvta_generic_to_shared(
            Qs + (warp * 16 + (lane & 15)) * QH + kf * 16 + (lane >> 4) * 8);
        LDSM_X4(qa[kf][0], qa[kf][1], qa[kf][2], qa[kf][3], ad);
    }

    float m0 = -1e30f, m1 = -1e30f, l0 = 0.f, l1 = 0.f;
    float oa[8][4];
#pragma unroll
    for (int dt = 0; dt < 8; dt++)
#pragma unroll
        for (int i = 0; i < 4; i++) oa[dt][i] = 0.f;

    for (int kt = 0; kt < 32; kt++) {
        const int s = kt & 1;
        if (kt + 1 < 32) load_kv(1 - s, kt + 1);

        const __half* Kd = Ks + s * 64 * KH;
        const __half* Vd = Vs + s * 64 * VH;

        // S = Q @ K^T
        float acc[8][4];
#pragma unroll
        for (int nt = 0; nt < 8; nt++)
#pragma unroll
            for (int i = 0; i < 4; i++) acc[nt][i] = 0.f;

        const int g = lane >> 3;
#pragma unroll
        for (int kf = 0; kf < 4; kf++) {
#pragma unroll
            for (int nb = 0; nb < 4; nb++) {
                uint32_t b0, b1, b2, b3;
                uint32_t bd = (uint32_t)__cvta_generic_to_shared(
                    Kd + (nb * 16 + (g >> 1) * 8 + (lane & 7)) * KH +
                    kf * 16 + (g & 1) * 8);
                LDSM_X4(b0, b1, b2, b3, bd);
                MMA_F16(acc[2*nb],   qa[kf][0], qa[kf][1], qa[kf][2], qa[kf][3], b0, b1);
                MMA_F16(acc[2*nb+1], qa[kf][0], qa[kf][1], qa[kf][2], qa[kf][3], b2, b3);
            }
        }

        // online softmax (rows lr and lr+8)
        float mx0 = -1e30f, mx1 = -1e30f;
#pragma unroll
        for (int nt = 0; nt < 8; nt++) {
            mx0 = fmaxf(mx0, fmaxf(acc[nt][0], acc[nt][1]));
            mx1 = fmaxf(mx1, fmaxf(acc[nt][2], acc[nt][3]));
        }
        mx0 = fmaxf(mx0, __shfl_xor_sync(0xffffffffu, mx0, 1));
        mx0 = fmaxf(mx0, __shfl_xor_sync(0xffffffffu, mx0, 2));
        mx1 = fmaxf(mx1, __shfl_xor_sync(0xffffffffu, mx1, 1));
        mx1 = fmaxf(mx1, __shfl_xor_sync(0xffffffffu, mx1, 2));
        const float mn0 = fmaxf(m0, mx0), mn1 = fmaxf(m1, mx1);
        const float al0 = __expf(m0 - mn0), al1 = __expf(m1 - mn1);
        m0 = mn0; m1 = mn1;
        float rs0 = 0.f, rs1 = 0.f;
#pragma unroll
        for (int nt = 0; nt < 8; nt++) {
            acc[nt][0] = __expf(acc[nt][0] - mn0);
            acc[nt][1] = __expf(acc[nt][1] - mn0);
            acc[nt][2] = __expf(acc[nt][2] - mn1);
            acc[nt][3] = __expf(acc[nt][3] - mn1);
            rs0 += acc[nt][0] + acc[nt][1];
            rs1 += acc[nt][2] + acc[nt][3];
        }
        rs0 += __shfl_xor_sync(0xffffffffu, rs0, 1);
        rs0 += __shfl_xor_sync(0xffffffffu, rs0, 2);
        rs1 += __shfl_xor_sync(0xffffffffu, rs1, 1);
        rs1 += __shfl_xor_sync(0xffffffffu, rs1, 2);
        l0 = l0 * al0 + rs0;
        l1 = l1 * al1 + rs1;
#pragma unroll
        for (int dt = 0; dt < 8; dt++) {
            oa[dt][0] *= al0; oa[dt][1] *= al0;
            oa[dt][2] *= al1; oa[dt][3] *= al1;
        }

        // O += P @ V  (P packed straight from registers — acc frag == A frag)
#pragma unroll
        for (int c = 0; c < 4; c++) {
            const uint32_t a0 = pack_h2f(acc[2*c][0],   acc[2*c][1]);
            const uint32_t a1 = pack_h2f(acc[2*c][2],   acc[2*c][3]);
            const uint32_t a2 = pack_h2f(acc[2*c+1][0], acc[2*c+1][1]);
            const uint32_t a3 = pack_h2f(acc[2*c+1][2], acc[2*c+1][3]);
#pragma unroll
            for (int nb = 0; nb < 4; nb++) {
                uint32_t v0, v1, v2, v3;
                uint32_t vd = (uint32_t)__cvta_generic_to_shared(
                    Vd + (c * 16 + (lane & 15)) * VH + nb * 16 + (lane >> 4) * 8);
                LDSM_X4T(v0, v1, v2, v3, vd);
                MMA_F16(oa[2*nb],   a0, a1, a2, a3, v0, v1);
                MMA_F16(oa[2*nb+1], a0, a1, a2, a3, v2, v3);
            }
        }

        if (kt + 1 < 32) {
            asm volatile("cp.async.wait_group 0;\n");
            __syncthreads();
        }
    }

    const float i0 = 1.f / l0, i1 = 1.f / l1;
    __half* ob = o + (size_t)(b * 2048 + qt * 128 + warp * 16 + lr) * C_DIM + h * D_DIM;
#pragma unroll
    for (int dt = 0; dt < 8; dt++) {
        *(uint32_t*)(ob + dt * 8 + 2 * lc) =
            pack_h2f(oa[dt][0] * i0, oa[dt][1] * i0);
        *(uint32_t*)(ob + 8 * C_DIM + dt * 8 + 2 * lc) =
            pack_h2f(oa[dt][2] * i1, oa[dt][3] * i1);
    }
}

// ---------------- h2 = silu(g)*vv, zero padded, half ----------------
__global__ void __launch_bounds__(256) k_silu_h2(
    const __half* __restrict__ vg, __half* __restrict__ h2)
{
    const int r = blockIdx.x;
    const __half* vr = vg + (size_t)r * VG_P;
    __half* hr = h2 + (size_t)r * INNER_P;
    for (int c = threadIdx.x; c < INNER_P; c += 256) {
        float out = 0.f;
        if (c < INNER) {
            const float vv = __half2float(vr[c]);
            const float g = __half2float(vr[INNER + c]);
            out = vv * g / (1.f + __expf(-g));
        }
        hr[c] = __float2half(out);
    }
}

// ---------------- mlps = half(silu(mlp_h)) ----------------
__global__ void __launch_bounds__(256) k_silu_mlp(
    const __half* __restrict__ fused, __half* __restrict__ mlps)
{
    const int r = blockIdx.x;
    const __half* src = fused + (size_t)r * FUSED_N + 3 * C_DIM;
    __half* dst = mlps + (size_t)r * MLP_DIM;
    for (int c = threadIdx.x; c < MLP_DIM; c += 256) {
        const float g = __half2float(src[c]);
        dst[c] = __float2half(g / (1.f + __expf(-g)));
    }
}

// ---------------- gate = tanh(x @ W_g + b_g) ----------------
__global__ void __launch_bounds__(256) k_gate(
    const float* __restrict__ x, const float* __restrict__ Wg,
    const float* __restrict__ bg, float* __restrict__ gate)
{
    __shared__ float xs[1024];
    __shared__ float part[16][17];
    const int r = blockIdx.x, tid = threadIdx.x;
    *(float4*)&xs[tid * 4] = ((const float4*)(x + (size_t)r * C_DIM))[tid];
    __syncthreads();
    const int h = tid & 15, seg = tid >> 4;
    float s = 0.f;
#pragma unroll 8
    for (int c = seg * 64; c < seg * 64 + 64; c++) s += xs[c] * Wg[c * 16 + h];
    part[h][seg] = s;
    __syncthreads();
    if (tid < 16) {
        float t = bg[tid];
#pragma unroll
        for (int sg = 0; sg < 16; sg++) t += part[tid][sg];
        gate[(size_t)r * 16 + tid] = tanhf(t);
    }
}

// ---------------- rms[b,h] over (n,d) of f ----------------
__global__ void __launch_bounds__(256) k_rms(const float* __restrict__ f, float* __restrict__ rms)
{
    const int b = blockIdx.x >> 4, h = blockIdx.x & 15;
    float s = 0.f;
    for (int n = threadIdx.x; n < 2048; n += 256) {
        const float4* fp = (const float4*)(f + (size_t)(b * 2048 + n) * C_DIM + h * D_DIM);
#pragma unroll
        for (int d4 = 0; d4 < 16; d4++) {
            const float4 v = fp[d4];
            s += v.x * v.x + v.y * v.y + v.z * v.z + v.w * v.w;
        }
    }
    s = block_reduce_sum(s);
    if (threadIdx.x == 0)
        rms[blockIdx.x] = fmaxf(sqrtf(s * (1.f / 131072.f)), 1e-6f);
}

// ---------------- o = half(o + gate * f / rms) ----------------
__global__ void __launch_bounds__(256) k_combine(
    __half* __restrict__ o, const float* __restrict__ f,
    const float* __restrict__ gate, const float* __restrict__ rms)
{
    const int r = blockIdx.x, tid = threadIdx.x;
    const int h = tid >> 4;
    const float g = gate[(size_t)r * 16 + h] / rms[(r >> 11) * 16 + h];
    __half2* op = (__half2*)(o + (size_t)r * C_DIM) + tid * 2;
    const float4 fv = ((const float4*)(f + (size_t)r * C_DIM))[tid];
    float2 a = __half22float2(op[0]);
    float2 bq = __half22float2(op[1]);
    a.x += g * fv.x; a.y += g * fv.y;
    bq.x += g * fv.z; bq.y += g * fv.w;
    op[0] = __floats2half2_rn(a.x, a.y);
    op[1] = __floats2half2_rn(bq.x, bq.y);
}

// ---------------- launch ----------------
extern "C" void kernel_launch(void* const* d_in, const int* in_sizes, int n_in,
                              void* d_out, int out_size)
{
    const float* x     = (const float*)d_in[0];
    const float* emb   = (const float*)d_in[1];
    const float* W_emb = (const float*)d_in[2];
    const float* b_emb = (const float*)d_in[3];
    const float* ln_w  = (const float*)d_in[4];
    const float* ln_b  = (const float*)d_in[5];
    const float* W_f   = (const float*)d_in[6];
    const float* b_f   = (const float*)d_in[7];
    const float* qn_w  = (const float*)d_in[8];
    const float* qn_b  = (const float*)d_in[9];
    const float* kn_w  = (const float*)d_in[10];
    const float* kn_b  = (const float*)d_in[11];
    const float* W_ao  = (const float*)d_in[12];
    const float* b_ao  = (const float*)d_in[13];
    const float* W_mo  = (const float*)d_in[14];
    const float* b_mo  = (const float*)d_in[15];
    const float* Wm_in = (const float*)d_in[16];
    const float* bm_in = (const float*)d_in[17];
    const float* Wm_out= (const float*)d_in[18];
    const float* bm_out= (const float*)d_in[19];
    const float* W_g   = (const float*)d_in[20];
    const float* b_g   = (const float*)d_in[21];
    float* out = (float*)d_out;

    float *se, *f, *gate, *rms, *x2, *bmin;
    __half *xn, *fused, *o, *vg, *h2, *mlps;
    __half *embt, *Wembt, *Wft, *Wmint, *Wmot, *Waot, *Wmo2t;
    cudaGetSymbolAddress((void**)&se,    g_se);
    cudaGetSymbolAddress((void**)&xn,    g_xn);
    cudaGetSymbolAddress((void**)&fused, g_fused);
    cudaGetSymbolAddress((void**)&o,     g_o);
    cudaGetSymbolAddress((void**)&vg,    g_vg);
    cudaGetSymbolAddress((void**)&h2,    g_h2);
    cudaGetSymbolAddress((void**)&mlps,  g_mlps);
    cudaGetSymbolAddress((void**)&f,     g_f);
    cudaGetSymbolAddress((void**)&gate,  g_gate);
    cudaGetSymbolAddress((void**)&rms,   g_rms);
    cudaGetSymbolAddress((void**)&x2,    g_x2);
    cudaGetSymbolAddress((void**)&embt,  g_embt);
    cudaGetSymbolAddress((void**)&Wembt, g_Wembt);
    cudaGetSymbolAddress((void**)&Wft,   g_Wft);
    cudaGetSymbolAddress((void**)&Wmint, g_Wmint);
    cudaGetSymbolAddress((void**)&bmin,  g_bmin);
    cudaGetSymbolAddress((void**)&Wmot,  g_Wmot);
    cudaGetSymbolAddress((void**)&Waot,  g_Waot);
    cudaGetSymbolAddress((void**)&Wmo2t, g_Wmo2t);

    cudaFuncSetAttribute(tgemm_h<__half, false>, cudaFuncAttributeMaxDynamicSharedMemorySize, GSMEM);
    cudaFuncSetAttribute(tgemm_h<float, false>,  cudaFuncAttributeMaxDynamicSharedMemorySize, GSMEM);
    cudaFuncSetAttribute(tgemm_h<float, true>,   cudaFuncAttributeMaxDynamicSharedMemorySize, GSMEM);
    cudaFuncSetAttribute(k_attn_h, cudaFuncAttributeMaxDynamicSharedMemorySize, ATT_SMEM);

    const int MB = T_ROWS / 128;  // 64
    dim3 blk(256);

    // --- half conversions (+ padding) ---
    k_cvth<<<dim3(C_DIM / 256, T_ROWS), blk>>>(emb,    embt,  T_ROWS, C_DIM, C_DIM);
    k_cvth<<<dim3(SE_N / 256, C_DIM), blk>>>(W_emb,  Wembt, C_DIM, SE_N, SE_N);
    k_cvth<<<dim3(FUSED_N / 256, C_DIM), blk>>>(W_f, Wft,   C_DIM, FUSED_N, FUSED_N);
    k_cvth<<<dim3((VG_P + 255) / 256, C_DIM), blk>>>(Wm_in, Wmint, C_DIM, 2 * INNER, VG_P);
    k_padf<<<dim3((VG_P + 255) / 256), blk>>>(bm_in, bmin, 2 * INNER, VG_P);
    k_cvth<<<dim3(C_DIM / 256, INNER_P), blk>>>(Wm_out, Wmot, INNER, C_DIM, C_DIM);
    k_cvth<<<dim3(C_DIM / 256, C_DIM), blk>>>(W_ao,  Waot,  C_DIM, C_DIM, C_DIM);
    k_cvth<<<dim3(C_DIM / 256, MLP_DIM), blk>>>(W_mo, Wmo2t, MLP_DIM, C_DIM, C_DIM);

    // 1) se = emb @ W_emb + b_emb   (fp32 out)
    tgemm_h<float, false><<<dim3(SE_N / 128, MB), blk, GSMEM>>>(
        embt, C_DIM, Wembt, SE_N, b_emb, nullptr, 0, se, SE_N, C_DIM);

    // 2) xn = LN(x)*(1+scale)+shift  (half out)
    k_lnmod<<<T_ROWS, blk>>>(x, ln_w, ln_b, se, xn);

    // 3) fused = xn @ W_f + b_f  (half out)
    tgemm_h<__half, false><<<dim3(FUSED_N / 128, MB), blk, GSMEM>>>(
        xn, C_DIM, Wft, FUSED_N, b_f, nullptr, 0, fused, FUSED_N, C_DIM);

    // 4) per-head LN of q,k in place
    k_qkln<<<T_ROWS * H_DIM / 8, blk>>>(fused, qn_w, qn_b, kn_w, kn_b);

    // 5) fp16 tensor-core flash attention -> o [B,N,H,D] (half)
    k_attn_h<<<dim3(16, 64), blk, ATT_SMEM>>>(fused, o);

    // 6) vg = qp @ Wm_in + bm_in  (half out)
    tgemm_h<__half, false><<<dim3(VG_P / 128, MB), blk, GSMEM>>>(
        fused, FUSED_N, Wmint, VG_P, bmin, nullptr, 0, vg, VG_P, C_DIM);

    // 7) h2 = silu(g)*vv ; mlps = silu(mlp_h)
    k_silu_h2<<<T_ROWS, blk>>>(vg, h2);
    k_silu_mlp<<<T_ROWS, blk>>>(fused, mlps);

    // 8) f = h2 @ Wm_out + bm_out  (fp32 out)
    tgemm_h<float, false><<<dim3(C_DIM / 128, MB), blk, GSMEM>>>(
        h2, INNER_P, Wmot, C_DIM, bm_out, nullptr, 0, f, C_DIM, INNER_P);

    // 9) gate, rms, combine (o half updated in place)
    k_gate<<<T_ROWS, blk>>>(x, W_g, b_g, gate);
    k_rms<<<4 * H_DIM, blk>>>(f, rms);
    k_combine<<<T_ROWS, blk>>>(o, f, gate, rms);

    // 10) x2 = x + o @ W_ao + b_ao  (fp32 out)
    tgemm_h<float, true><<<dim3(C_DIM / 128, MB), blk, GSMEM>>>(
        o, C_DIM, Waot, C_DIM, b_ao, x, C_DIM, x2, C_DIM, C_DIM);

    // 11) out = x2 + mlps @ W_mo + b_mo  (fp32 out)
    tgemm_h<float, true><<<dim3(C_DIM / 128, MB), blk, GSMEM>>>(
        mlps, MLP_DIM, Wmo2t, C_DIM, b_mo, x2, C_DIM, out, C_DIM, MLP_DIM);
}

// round 6
// speedup vs baseline: 2.7112x; 1.0523x over previous
#include <cuda_runtime.h>
#include <cuda_fp16.h>
#include <math.h>
#include <stdint.h>

// Problem constants
#define T_ROWS   8192            // B*N
#define C_DIM    1024
#define H_DIM    16
#define D_DIM    64
#define FUSED_N  7168            // 3C + MLP
#define QKV_N    3072
#define SE_N     2048
#define MLP_DIM  4096
#define INNER    2730
#define INNER_P  2752            // padded (mult of 32)
#define VG_P     5504            // 2*INNER_P (paired layout)

// ---------------- scratch (static device allocations) ----------------
__device__ __half g_se   [T_ROWS * SE_N];
__device__ __half g_xn   [T_ROWS * C_DIM];
__device__ __half g_qkv  [(size_t)T_ROWS * QKV_N];
__device__ __half g_o    [T_ROWS * C_DIM];
__device__ __half g_h2   [(size_t)T_ROWS * INNER_P];
__device__ __half g_mlps [(size_t)T_ROWS * MLP_DIM];
__device__ float  g_f    [T_ROWS * C_DIM];
__device__ float  g_gate [T_ROWS * H_DIM];
__device__ float  g_rms  [4 * H_DIM];
__device__ float  g_x2   [T_ROWS * C_DIM];
// half-converted (and padded / paired) operands
__device__ __half g_embt [T_ROWS * C_DIM];
__device__ __half g_Wembt[C_DIM * SE_N];
__device__ __half g_Wft  [(size_t)C_DIM * FUSED_N];
__device__ __half g_Wmint[(size_t)C_DIM * VG_P];   // paired [vv|g] layout
__device__ float  g_bmin [VG_P];                    // paired bias
__device__ __half g_Wmot [INNER_P * C_DIM];
__device__ __half g_Waot [C_DIM * C_DIM];
__device__ __half g_Wmo2t[MLP_DIM * C_DIM];

__device__ __forceinline__ uint32_t pack_h2f(float lo, float hi)
{
    uint32_t u;
    asm("cvt.rn.f16x2.f32 %0, %1, %2;" : "=r"(u) : "f"(hi), "f"(lo));
    return u;
}

// ---------------- convert + pad ----------------
__global__ void __launch_bounds__(256) k_cvth(
    const float* __restrict__ in, __half* __restrict__ out,
    int rows_in, int cols_in, int cols_out)
{
    const int r = blockIdx.y;
    const int c = blockIdx.x * 256 + threadIdx.x;
    if (c >= cols_out) return;
    float v = (c < cols_in && r < rows_in) ? in[(size_t)r * cols_in + c] : 0.f;
    out[(size_t)r * cols_out + c] = __float2half(v);
}

// Wm_in columns interleaved: out col 2c = vv col c, out col 2c+1 = g col c
__global__ void __launch_bounds__(256) k_cvt_gluW(
    const float* __restrict__ in, __half* __restrict__ out)
{
    const int r = blockIdx.y;
    const int c = blockIdx.x * 256 + threadIdx.x;
    if (c >= VG_P) return;
    const int pair = c >> 1, isg = c & 1;
    float v = 0.f;
    if (pair < INNER) v = in[(size_t)r * (2 * INNER) + (isg ? INNER + pair : pair)];
    out[(size_t)r * VG_P + c] = __float2half(v);
}

__global__ void __launch_bounds__(256) k_pad_glub(
    const float* __restrict__ in, float* __restrict__ out)
{
    const int c = blockIdx.x * 256 + threadIdx.x;
    if (c >= VG_P) return;
    const int pair = c >> 1, isg = c & 1;
    out[c] = (pair < INNER) ? in[isg ? INNER + pair : pair] : 0.f;
}

// ---------------- fp16 tensor-core GEMM, 128x128x32, 3-stage cp.async ------
#define BM 128
#define BN 128
#define BK 32
#define NSTG 3
#define AH 40
#define BH 136
#define GSMEM ((NSTG*BM*AH + NSTG*BK*BH) * (int)sizeof(__half))

#define MMA_F16(D, A0,A1,A2,A3, B0,B1)                                        \
    asm volatile(                                                             \
        "mma.sync.aligned.m16n8k16.row.col.f32.f16.f16.f32 "                  \
        "{%0,%1,%2,%3}, {%4,%5,%6,%7}, {%8,%9}, {%0,%1,%2,%3};\n"            \
        : "+f"((D)[0]), "+f"((D)[1]), "+f"((D)[2]), "+f"((D)[3])              \
        : "r"(A0), "r"(A1), "r"(A2), "r"(A3), "r"(B0), "r"(B1))

#define LDSM_X4(R0,R1,R2,R3, ADDR)                                            \
    asm volatile("ldmatrix.sync.aligned.m8n8.x4.shared.b16 "                  \
                 "{%0,%1,%2,%3}, [%4];"                                       \
                 : "=r"(R0), "=r"(R1), "=r"(R2), "=r"(R3) : "r"(ADDR))

#define LDSM_X4T(R0,R1,R2,R3, ADDR)                                           \
    asm volatile("ldmatrix.sync.aligned.m8n8.x4.trans.shared.b16 "            \
                 "{%0,%1,%2,%3}, [%4];"                                       \
                 : "=r"(R0), "=r"(R1), "=r"(R2), "=r"(R3) : "r"(ADDR))

__device__ __forceinline__ float siluf(float g) { return g / (1.f + __expf(-g)); }

// EPI: 0 = none, 1 = silu(v) (half out), 2 = GLU pair silu(g)*vv -> half at gn/2
template<typename OutT, bool RESID, int EPI>
__global__ void __launch_bounds__(256) tgemm_h(
    const __half* __restrict__ A, int lda,
    const __half* __restrict__ B, int ldb,
    const float* __restrict__ bias,
    const float* __restrict__ R, int ldr,
    OutT* __restrict__ C, int ldc,
    int K)
{
    extern __shared__ __half sh[];
    __half* As = sh;
    __half* Bs = sh + NSTG * BM * AH;

    const int tid  = threadIdx.x;
    const int warp = tid >> 5, lane = tid & 31;
    const int wm = warp & 1, wn = warp >> 1;
    const int lr = lane >> 2, lc = lane & 3;
    const int bx = blockIdx.x, by = blockIdx.y;

    const int arow = tid >> 1;
    const int acol = (tid & 1) * 16;
    const int brow = tid >> 3;
    const int bcol = (tid & 7) * 8;

    const __half* Ag = A + (size_t)(by * BM + arow) * lda + acol;
    const __half* Bg = B + (size_t)brow * ldb + bx * BN + bcol;

    auto load_tile = [&](int stg, int k0) {
        __half* Asd = As + stg * BM * AH;
        __half* Bsd = Bs + stg * BK * BH;
        uint32_t d0 = (uint32_t)__cvta_generic_to_shared(Asd + arow * AH + acol);
        asm volatile("cp.async.cg.shared.global [%0], [%1], 16;\n"
                     :: "r"(d0), "l"(Ag + k0));
        asm volatile("cp.async.cg.shared.global [%0], [%1], 16;\n"
                     :: "r"(d0 + 16), "l"(Ag + k0 + 8));
        uint32_t d1 = (uint32_t)__cvta_generic_to_shared(Bsd + brow * BH + bcol);
        asm volatile("cp.async.cg.shared.global [%0], [%1], 16;\n"
                     :: "r"(d1), "l"(Bg + (size_t)k0 * ldb));
        asm volatile("cp.async.cg.shared.global [%0], [%1], 16;\n"
                     :: "r"(d1 + 128), "l"(Bg + (size_t)k0 * ldb + 64));
        asm volatile("cp.async.commit_group;\n");
    };

    float acc[4][4][4];
#pragma unroll
    for (int mt = 0; mt < 4; mt++)
#pragma unroll
        for (int nt = 0; nt < 4; nt++)
#pragma unroll
            for (int i = 0; i < 4; i++) acc[mt][nt][i] = 0.f;

    const int ntiles = K / BK;
    load_tile(0, 0);
    load_tile(1, BK);
    asm volatile("cp.async.wait_group 1;\n");
    __syncthreads();

    for (int kt = 0; kt < ntiles; kt++) {
        const int stg = kt % NSTG;
        if (kt + 2 < ntiles) load_tile((kt + 2) % NSTG, (kt + 2) * BK);

        const __half* Asd = As + stg * BM * AH;
        const __half* Bsd = Bs + stg * BK * BH;

#pragma unroll
        for (int kf = 0; kf < 2; kf++) {
            uint32_t af[4][4];
#pragma unroll
            for (int mt = 0; mt < 4; mt++) {
                uint32_t ad = (uint32_t)__cvta_generic_to_shared(
                    Asd + (wm * 64 + mt * 16 + (lane & 15)) * AH +
                    kf * 16 + (lane >> 4) * 8);
                LDSM_X4(af[mt][0], af[mt][1], af[mt][2], af[mt][3], ad);
            }
            uint32_t bf[4][2];
#pragma unroll
            for (int nb = 0; nb < 2; nb++) {
                uint32_t bd = (uint32_t)__cvta_generic_to_shared(
                    Bsd + (kf * 16 + (lane & 15)) * BH +
                    wn * 32 + nb * 16 + (lane >> 4) * 8);
                LDSM_X4T(bf[2*nb][0], bf[2*nb][1], bf[2*nb+1][0], bf[2*nb+1][1], bd);
            }
#pragma unroll
            for (int mt = 0; mt < 4; mt++)
#pragma unroll
                for (int nt = 0; nt < 4; nt++)
                    MMA_F16(acc[mt][nt], af[mt][0], af[mt][1], af[mt][2], af[mt][3],
                            bf[nt][0], bf[nt][1]);
        }
        if (kt + 1 < ntiles) {
            asm volatile("cp.async.wait_group 1;\n");
            __syncthreads();
        }
    }

#pragma unroll
    for (int mt = 0; mt < 4; mt++) {
        const int gm = by * BM + wm * 64 + mt * 16 + lr;
#pragma unroll
        for (int nt = 0; nt < 4; nt++) {
            const int gn = bx * BN + wn * 32 + nt * 8 + lc * 2;
            const float b0 = bias[gn], b1 = bias[gn + 1];
            float v00 = acc[mt][nt][0] + b0, v01 = acc[mt][nt][1] + b1;
            float v10 = acc[mt][nt][2] + b0, v11 = acc[mt][nt][3] + b1;
            if (EPI == 2) {
                // GLU: (vv, g) pair -> silu(g)*vv at column gn/2
                __half* Ch = (__half*)C;
                Ch[(size_t)gm * ldc + (gn >> 1)]       = __float2half(v00 * siluf(v01));
                Ch[(size_t)(gm + 8) * ldc + (gn >> 1)] = __float2half(v10 * siluf(v11));
                continue;
            }
            if (RESID) {
                float2 r0 = *(const float2*)(R + (size_t)gm * ldr + gn);
                float2 r1 = *(const float2*)(R + (size_t)(gm + 8) * ldr + gn);
                v00 += r0.x; v01 += r0.y;
                v10 += r1.x; v11 += r1.y;
            }
            if (EPI == 1) {
                v00 = siluf(v00); v01 = siluf(v01);
                v10 = siluf(v10); v11 = siluf(v11);
            }
            if (sizeof(OutT) == 2) {
                *(uint32_t*)((__half*)C + (size_t)gm * ldc + gn) = pack_h2f(v00, v01);
                *(uint32_t*)((__half*)C + (size_t)(gm + 8) * ldc + gn) = pack_h2f(v10, v11);
            } else {
                *(float2*)((float*)C + (size_t)gm * ldc + gn) = make_float2(v00, v01);
                *(float2*)((float*)C + (size_t)(gm + 8) * ldc + gn) = make_float2(v10, v11);
            }
        }
    }
}

// ---------------- block reduce helper ----------------
__device__ __forceinline__ float block_reduce_sum(float v)
{
    __shared__ float shr[32];
    const int lane = threadIdx.x & 31, wid = threadIdx.x >> 5;
#pragma unroll
    for (int o = 16; o > 0; o >>= 1) v += __shfl_xor_sync(0xffffffffu, v, o);
    __syncthreads();
    if (lane == 0) shr[wid] = v;
    __syncthreads();
    const int nw = blockDim.x >> 5;
    float r = (threadIdx.x < nw) ? shr[threadIdx.x] : 0.f;
    if (wid == 0) {
#pragma unroll
        for (int o = 16; o > 0; o >>= 1) r += __shfl_xor_sync(0xffffffffu, r, o);
        if (lane == 0) shr[0] = r;
    }
    __syncthreads();
    return shr[0];
}

// ---------------- LN(x)*(1+scale)+shift -> half (se is half) ---------------
__global__ void __launch_bounds__(256) k_lnmod(
    const float* __restrict__ x, const float* __restrict__ lnw,
    const float* __restrict__ lnb, const __half* __restrict__ se,
    __half* __restrict__ xn)
{
    const int r = blockIdx.x, tid = threadIdx.x;
    const float4 v = ((const float4*)(x + (size_t)r * C_DIM))[tid];
    float s = v.x + v.y + v.z + v.w;
    s = block_reduce_sum(s);
    const float mu = s * (1.f / 1024.f);
    const float dx0 = v.x - mu, dx1 = v.y - mu, dx2 = v.z - mu, dx3 = v.w - mu;
    float q = dx0 * dx0 + dx1 * dx1 + dx2 * dx2 + dx3 * dx3;
    q = block_reduce_sum(q);
    const float rstd = rsqrtf(q * (1.f / 1024.f) + 1e-5f);
    const float4 w = ((const float4*)lnw)[tid];
    const float4 bb = ((const float4*)lnb)[tid];
    const __half2* sep = (const __half2*)(se + (size_t)r * SE_N);
    const float2 sc01 = __half22float2(sep[tid * 2]);
    const float2 sc23 = __half22float2(sep[tid * 2 + 1]);
    const float2 sf01 = __half22float2(sep[512 + tid * 2]);
    const float2 sf23 = __half22float2(sep[512 + tid * 2 + 1]);
    const float o0 = (dx0 * rstd * w.x + bb.x) * (1.f + sc01.x) + sf01.x;
    const float o1 = (dx1 * rstd * w.y + bb.y) * (1.f + sc01.y) + sf01.y;
    const float o2 = (dx2 * rstd * w.z + bb.z) * (1.f + sc23.x) + sf23.x;
    const float o3 = (dx3 * rstd * w.w + bb.w) * (1.f + sc23.y) + sf23.y;
    ((uint2*)(xn + (size_t)r * C_DIM))[tid] =
        make_uint2(pack_h2f(o0, o1), pack_h2f(o2, o3));
}

// ---------------- per-head LN of q,k (in place in qkv, half) ---------------
__global__ void __launch_bounds__(256) k_qkln(
    __half* __restrict__ qkv,
    const float* __restrict__ qw, const float* __restrict__ qb,
    const float* __restrict__ kw, const float* __restrict__ kb)
{
    const int w = threadIdx.x >> 5, lane = threadIdx.x & 31;
    const int idx = blockIdx.x * 8 + w;
    const int r = idx >> 4, h = idx & 15;
    __half* base = qkv + (size_t)r * QKV_N + h * D_DIM;
#pragma unroll
    for (int part = 0; part < 2; part++) {
        __half* p = base + part * C_DIM;
        float v0 = __half2float(p[lane]), v1 = __half2float(p[lane + 32]);
        float s = v0 + v1;
#pragma unroll
        for (int o = 16; o > 0; o >>= 1) s += __shfl_xor_sync(0xffffffffu, s, o);
        const float mu = s * (1.f / 64.f);
        const float d0 = v0 - mu, d1 = v1 - mu;
        float q = d0 * d0 + d1 * d1;
#pragma unroll
        for (int o = 16; o > 0; o >>= 1) q += __shfl_xor_sync(0xffffffffu, q, o);
        const float rstd = rsqrtf(q * (1.f / 64.f) + 1e-5f);
        const float* ww = part ? kw : qw;
        const float* bb = part ? kb : qb;
        p[lane]      = __float2half(d0 * rstd * ww[lane]      + bb[lane]);
        p[lane + 32] = __float2half(d1 * rstd * ww[lane + 32] + bb[lane + 32]);
    }
}

// ---------------- fp16 tensor-core flash attention ----------------
#define QH 72
#define KH 72
#define VH 72
#define ATT_SMEM ((128*QH + 2*64*KH + 2*64*VH) * (int)sizeof(__half))

__global__ void __launch_bounds__(256) k_attn_h(
    const __half* __restrict__ qkv, __half* __restrict__ o)
{
    extern __shared__ __half shh[];
    __half* Qs = shh;                      // [128][QH]
    __half* Ks = Qs + 128 * QH;            // [2][64][KH]
    __half* Vs = Ks + 2 * 64 * KH;         // [2][64][VH]

    const int qt = blockIdx.x, bh = blockIdx.y;
    const int b = bh >> 4, h = bh & 15;
    const int tid = threadIdx.x;
    const int warp = tid >> 5, lane = tid & 31;
    const int lr = lane >> 2, lc = lane & 3;

    const __half* qbase = qkv + (size_t)(b * 2048 + qt * 128) * QKV_N + h * D_DIM;
    const __half2 scl = __float2half2_rn(0.125f);
    for (int it = tid; it < 4096; it += 256) {
        const int r = it >> 5, c = (it & 31) * 2;
        __half2 v = *(const __half2*)(qbase + (size_t)r * QKV_N + c);
        *(__half2*)(Qs + r * QH + c) = __hmul2(v, scl);
    }

    auto load_kv = [&](int s, int kt) {
        const __half* kb = qkv + (size_t)(b * 2048 + kt * 64) * QKV_N + C_DIM + h * D_DIM;
        const __half* vb = kb + C_DIM;
        __half* Kd = Ks + s * 64 * KH;
        __half* Vd = Vs + s * 64 * VH;
        for (int it = tid; it < 512; it += 256) {
            const int r = it >> 3, c = (it & 7) * 8;
            uint32_t dk = (uint32_t)__cvta_generic_to_shared(Kd + r * KH + c);
            asm volatile("cp.async.cg.shared.global [%0], [%1], 16;\n"
                         :: "r"(dk), "l"(kb + (size_t)r * QKV_N + c));
            uint32_t dv = (uint32_t)__cvta_generic_to_shared(Vd + r * VH + c);
            asm volatile("cp.async.cg.shared.global [%0], [%1], 16;\n"
                         :: "r"(dv), "l"(vb + (size_t)r * QKV_N + c));
        }
        asm volatile("cp.async.commit_group;\n");
    };

    load_kv(0, 0);
    asm volatile("cp.async.wait_group 0;\n");
    __syncthreads();

    uint32_t qa[4][4];
#pragma unroll
    for (int kf = 0; kf < 4; kf++) {
        uint32_t ad = (uint32_t)__cvta_generic_to_shared(
            Qs + (warp * 16 + (lane & 15)) * QH + kf * 16 + (lane >> 4) * 8);
        LDSM_X4(qa[kf][0], qa[kf][1], qa[kf][2], qa[kf][3], ad);
    }

    float m0 = -1e30f, m1 = -1e30f, l0 = 0.f, l1 = 0.f;
    float oa[8][4];
#pragma unroll
    for (int dt = 0; dt < 8; dt++)
#pragma unroll
        for (int i = 0; i < 4; i++) oa[dt][i] = 0.f;

    for (int kt = 0; kt < 32; kt++) {
        const int s = kt & 1;
        if (kt + 1 < 32) load_kv(1 - s, kt + 1);

        const __half* Kd = Ks + s * 64 * KH;
        const __half* Vd = Vs + s * 64 * VH;

        float acc[8][4];
#pragma unroll
        for (int nt = 0; nt < 8; nt++)
#pragma unroll
            for (int i = 0; i < 4; i++) acc[nt][i] = 0.f;

        const int g = lane >> 3;
#pragma unroll
        for (int kf = 0; kf < 4; kf++) {
#pragma unroll
            for (int nb = 0; nb < 4; nb++) {
                uint32_t b0, b1, b2, b3;
                uint32_t bd = (uint32_t)__cvta_generic_to_shared(
                    Kd + (nb * 16 + (g >> 1) * 8 + (lane & 7)) * KH +
                    kf * 16 + (g & 1) * 8);
                LDSM_X4(b0, b1, b2, b3, bd);
                MMA_F16(acc[2*nb],   qa[kf][0], qa[kf][1], qa[kf][2], qa[kf][3], b0, b1);
                MMA_F16(acc[2*nb+1], qa[kf][0], qa[kf][1], qa[kf][2], qa[kf][3], b2, b3);
            }
        }

        float mx0 = -1e30f, mx1 = -1e30f;
#pragma unroll
        for (int nt = 0; nt < 8; nt++) {
            mx0 = fmaxf(mx0, fmaxf(acc[nt][0], acc[nt][1]));
            mx1 = fmaxf(mx1, fmaxf(acc[nt][2], acc[nt][3]));
        }
        mx0 = fmaxf(mx0, __shfl_xor_sync(0xffffffffu, mx0, 1));
        mx0 = fmaxf(mx0, __shfl_xor_sync(0xffffffffu, mx0, 2));
        mx1 = fmaxf(mx1, __shfl_xor_sync(0xffffffffu, mx1, 1));
        mx1 = fmaxf(mx1, __shfl_xor_sync(0xffffffffu, mx1, 2));
        const float mn0 = fmaxf(m0, mx0), mn1 = fmaxf(m1, mx1);
        const float al0 = __expf(m0 - mn0), al1 = __expf(m1 - mn1);
        m0 = mn0; m1 = mn1;
        float rs0 = 0.f, rs1 = 0.f;
#pragma unroll
        for (int nt = 0; nt < 8; nt++) {
            acc[nt][0] = __expf(acc[nt][0] - mn0);
            acc[nt][1] = __expf(acc[nt][1] - mn0);
            acc[nt][2] = __expf(acc[nt][2] - mn1);
            acc[nt][3] = __expf(acc[nt][3] - mn1);
            rs0 += acc[nt][0] + acc[nt][1];
            rs1 += acc[nt][2] + acc[nt][3];
        }
        rs0 += __shfl_xor_sync(0xffffffffu, rs0, 1);
        rs0 += __shfl_xor_sync(0xffffffffu, rs0, 2);
        rs1 += __shfl_xor_sync(0xffffffffu, rs1, 1);
        rs1 += __shfl_xor_sync(0xffffffffu, rs1, 2);
        l0 = l0 * al0 + rs0;
        l1 = l1 * al1 + rs1;
#pragma unroll
        for (int dt = 0; dt < 8; dt++) {
            oa[dt][0] *= al0; oa[dt][1] *= al0;
            oa[dt][2] *= al1; oa[dt][3] *= al1;
        }

#pragma unroll
        for (int c = 0; c < 4; c++) {
            const uint32_t a0 = pack_h2f(acc[2*c][0],   acc[2*c][1]);
            const uint32_t a1 = pack_h2f(acc[2*c][2],   acc[2*c][3]);
            const uint32_t a2 = pack_h2f(acc[2*c+1][0], acc[2*c+1][1]);
            const uint32_t a3 = pack_h2f(acc[2*c+1][2], acc[2*c+1][3]);
#pragma unroll
            for (int nb = 0; nb < 4; nb++) {
                uint32_t v0, v1, v2, v3;
                uint32_t vd = (uint32_t)__cvta_generic_to_shared(
                    Vd + (c * 16 + (lane & 15)) * VH + nb * 16 + (lane >> 4) * 8);
                LDSM_X4T(v0, v1, v2, v3, vd);
                MMA_F16(oa[2*nb],   a0, a1, a2, a3, v0, v1);
                MMA_F16(oa[2*nb+1], a0, a1, a2, a3, v2, v3);
            }
        }

        if (kt + 1 < 32) {
            asm volatile("cp.async.wait_group 0;\n");
            __syncthreads();
        }
    }

    const float i0 = 1.f / l0, i1 = 1.f / l1;
    __half* ob = o + (size_t)(b * 2048 + qt * 128 + warp * 16 + lr) * C_DIM + h * D_DIM;
#pragma unroll
    for (int dt = 0; dt < 8; dt++) {
        *(uint32_t*)(ob + dt * 8 + 2 * lc) =
            pack_h2f(oa[dt][0] * i0, oa[dt][1] * i0);
        *(uint32_t*)(ob + 8 * C_DIM + dt * 8 + 2 * lc) =
            pack_h2f(oa[dt][2] * i1, oa[dt][3] * i1);
    }
}

// ---------------- gate = tanh(x @ W_g + b_g) ----------------
__global__ void __launch_bounds__(256) k_gate(
    const float* __restrict__ x, const float* __restrict__ Wg,
    const float* __restrict__ bg, float* __restrict__ gate)
{
    __shared__ float xs[1024];
    __shared__ float part[16][17];
    const int r = blockIdx.x, tid = threadIdx.x;
    *(float4*)&xs[tid * 4] = ((const float4*)(x + (size_t)r * C_DIM))[tid];
    __syncthreads();
    const int h = tid & 15, seg = tid >> 4;
    float s = 0.f;
#pragma unroll 8
    for (int c = seg * 64; c < seg * 64 + 64; c++) s += xs[c] * Wg[c * 16 + h];
    part[h][seg] = s;
    __syncthreads();
    if (tid < 16) {
        float t = bg[tid];
#pragma unroll
        for (int sg = 0; sg < 16; sg++) t += part[tid][sg];
        gate[(size_t)r * 16 + tid] = tanhf(t);
    }
}

// ---------------- rms[b,h] over (n,d) of f ----------------
__global__ void __launch_bounds__(256) k_rms(const float* __restrict__ f, float* __restrict__ rms)
{
    const int b = blockIdx.x >> 4, h = blockIdx.x & 15;
    float s = 0.f;
    for (int n = threadIdx.x; n < 2048; n += 256) {
        const float4* fp = (const float4*)(f + (size_t)(b * 2048 + n) * C_DIM + h * D_DIM);
#pragma unroll
        for (int d4 = 0; d4 < 16; d4++) {
            const float4 v = fp[d4];
            s += v.x * v.x + v.y * v.y + v.z * v.z + v.w * v.w;
        }
    }
    s = block_reduce_sum(s);
    if (threadIdx.x == 0)
        rms[blockIdx.x] = fmaxf(sqrtf(s * (1.f / 131072.f)), 1e-6f);
}

// ---------------- o = half(o + gate * f / rms) ----------------
__global__ void __launch_bounds__(256) k_combine(
    __half* __restrict__ o, const float* __restrict__ f,
    const float* __restrict__ gate, const float* __restrict__ rms)
{
    const int r = blockIdx.x, tid = threadIdx.x;
    const int h = tid >> 4;
    const float g = gate[(size_t)r * 16 + h] / rms[(r >> 11) * 16 + h];
    __half2* op = (__half2*)(o + (size_t)r * C_DIM) + tid * 2;
    const float4 fv = ((const float4*)(f + (size_t)r * C_DIM))[tid];
    float2 a = __half22float2(op[0]);
    float2 bq = __half22float2(op[1]);
    a.x += g * fv.x; a.y += g * fv.y;
    bq.x += g * fv.z; bq.y += g * fv.w;
    op[0] = __floats2half2_rn(a.x, a.y);
    op[1] = __floats2half2_rn(bq.x, bq.y);
}

// ---------------- launch ----------------
extern "C" void kernel_launch(void* const* d_in, const int* in_sizes, int n_in,
                              void* d_out, int out_size)
{
    const float* x     = (const float*)d_in[0];
    const float* emb   = (const float*)d_in[1];
    const float* W_emb = (const float*)d_in[2];
    const float* b_emb = (const float*)d_in[3];
    const float* ln_w  = (const float*)d_in[4];
    const float* ln_b  = (const float*)d_in[5];
    const float* W_f   = (const float*)d_in[6];
    const float* b_f   = (const float*)d_in[7];
    const float* qn_w  = (const float*)d_in[8];
    const float* qn_b  = (const float*)d_in[9];
    const float* kn_w  = (const float*)d_in[10];
    const float* kn_b  = (const float*)d_in[11];
    const float* W_ao  = (const float*)d_in[12];
    const float* b_ao  = (const float*)d_in[13];
    const float* W_mo  = (const float*)d_in[14];
    const float* b_mo  = (const float*)d_in[15];
    const float* Wm_in = (const float*)d_in[16];
    const float* bm_in = (const float*)d_in[17];
    const float* Wm_out= (const float*)d_in[18];
    const float* bm_out= (const float*)d_in[19];
    const float* W_g   = (const float*)d_in[20];
    const float* b_g   = (const float*)d_in[21];
    float* out = (float*)d_out;

    float *f, *gate, *rms, *x2, *bmin;
    __half *se, *xn, *qkv, *o, *h2, *mlps;
    __half *embt, *Wembt, *Wft, *Wmint, *Wmot, *Waot, *Wmo2t;
    cudaGetSymbolAddress((void**)&se,    g_se);
    cudaGetSymbolAddress((void**)&xn,    g_xn);
    cudaGetSymbolAddress((void**)&qkv,   g_qkv);
    cudaGetSymbolAddress((void**)&o,     g_o);
    cudaGetSymbolAddress((void**)&h2,    g_h2);
    cudaGetSymbolAddress((void**)&mlps,  g_mlps);
    cudaGetSymbolAddress((void**)&f,     g_f);
    cudaGetSymbolAddress((void**)&gate,  g_gate);
    cudaGetSymbolAddress((void**)&rms,   g_rms);
    cudaGetSymbolAddress((void**)&x2,    g_x2);
    cudaGetSymbolAddress((void**)&embt,  g_embt);
    cudaGetSymbolAddress((void**)&Wembt, g_Wembt);
    cudaGetSymbolAddress((void**)&Wft,   g_Wft);
    cudaGetSymbolAddress((void**)&Wmint, g_Wmint);
    cudaGetSymbolAddress((void**)&bmin,  g_bmin);
    cudaGetSymbolAddress((void**)&Wmot,  g_Wmot);
    cudaGetSymbolAddress((void**)&Waot,  g_Waot);
    cudaGetSymbolAddress((void**)&Wmo2t, g_Wmo2t);

    cudaFuncSetAttribute(tgemm_h<__half, false, 0>, cudaFuncAttributeMaxDynamicSharedMemorySize, GSMEM);
    cudaFuncSetAttribute(tgemm_h<__half, false, 1>, cudaFuncAttributeMaxDynamicSharedMemorySize, GSMEM);
    cudaFuncSetAttribute(tgemm_h<__half, false, 2>, cudaFuncAttributeMaxDynamicSharedMemorySize, GSMEM);
    cudaFuncSetAttribute(tgemm_h<float, false, 0>,  cudaFuncAttributeMaxDynamicSharedMemorySize, GSMEM);
    cudaFuncSetAttribute(tgemm_h<float, true, 0>,   cudaFuncAttributeMaxDynamicSharedMemorySize, GSMEM);
    cudaFuncSetAttribute(k_attn_h, cudaFuncAttributeMaxDynamicSharedMemorySize, ATT_SMEM);

    const int MB = T_ROWS / 128;  // 64
    dim3 blk(256);

    // #1,#2: operand conversions for se GEMM
    k_cvth<<<dim3(C_DIM / 256, T_ROWS), blk>>>(emb, embt, T_ROWS, C_DIM, C_DIM);
    k_cvth<<<dim3(SE_N / 256, C_DIM), blk>>>(W_emb, Wembt, C_DIM, SE_N, SE_N);

    // #3: se = emb @ W_emb + b_emb  (half out)
    tgemm_h<__half, false, 0><<<dim3(SE_N / 128, MB), blk, GSMEM>>>(
        embt, C_DIM, Wembt, SE_N, b_emb, nullptr, 0, se, SE_N, C_DIM);

    // #4: xn = LN(x)*(1+scale)+shift  (half out)
    k_lnmod<<<T_ROWS, blk>>>(x, ln_w, ln_b, se, xn);

    // #5: W_f conversion
    k_cvth<<<dim3(FUSED_N / 256, C_DIM), blk>>>(W_f, Wft, C_DIM, FUSED_N, FUSED_N);

    // #6: qkv = xn @ W_f[:, :3072] + b_f[:3072]   <-- ncu capture target
    tgemm_h<__half, false, 0><<<dim3(QKV_N / 128, MB), blk, GSMEM>>>(
        xn, C_DIM, Wft, FUSED_N, b_f, nullptr, 0, qkv, QKV_N, C_DIM);

    // #7: mlps = silu(xn @ W_f[:, 3072:] + b_f[3072:])
    tgemm_h<__half, false, 1><<<dim3(MLP_DIM / 128, MB), blk, GSMEM>>>(
        xn, C_DIM, Wft + 3 * C_DIM, FUSED_N, b_f + 3 * C_DIM, nullptr, 0,
        mlps, MLP_DIM, C_DIM);

    // #8: per-head LN of q,k in place
    k_qkln<<<T_ROWS * H_DIM / 8, blk>>>(qkv, qn_w, qn_b, kn_w, kn_b);

    // #9: fp16 flash attention -> o [B,N,H,D]
    k_attn_h<<<dim3(16, 64), blk, ATT_SMEM>>>(qkv, o);

    // #10,#11: paired Wm_in / bias
    k_cvt_gluW<<<dim3((VG_P + 255) / 256, C_DIM), blk>>>(Wm_in, Wmint);
    k_pad_glub<<<dim3((VG_P + 255) / 256), blk>>>(bm_in, bmin);

    // #12: h2 = silu(g)*vv fused in GEMM epilogue (paired weights)
    tgemm_h<__half, false, 2><<<dim3(VG_P / 128, MB), blk, GSMEM>>>(
        qkv, QKV_N, Wmint, VG_P, bmin, nullptr, 0, h2, INNER_P, C_DIM);

    // #13: Wm_out conversion (zero-padded rows)
    k_cvth<<<dim3(C_DIM / 256, INNER_P), blk>>>(Wm_out, Wmot, INNER, C_DIM, C_DIM);

    // #14: f = h2 @ Wm_out + bm_out  (fp32 out)
    tgemm_h<float, false, 0><<<dim3(C_DIM / 128, MB), blk, GSMEM>>>(
        h2, INNER_P, Wmot, C_DIM, bm_out, nullptr, 0, f, C_DIM, INNER_P);

    // #15-17: gate, rms, combine
    k_gate<<<T_ROWS, blk>>>(x, W_g, b_g, gate);
    k_rms<<<4 * H_DIM, blk>>>(f, rms);
    k_combine<<<T_ROWS, blk>>>(o, f, gate, rms);

    // #18,#19: x2 = x + o @ W_ao + b_ao
    k_cvth<<<dim3(C_DIM / 256, C_DIM), blk>>>(W_ao, Waot, C_DIM, C_DIM, C_DIM);
    tgemm_h<float, true, 0><<<dim3(C_DIM / 128, MB), blk, GSMEM>>>(
        o, C_DIM, Waot, C_DIM, b_ao, x, C_DIM, x2, C_DIM, C_DIM);

    // #20,#21: out = x2 + mlps @ W_mo + b_mo
    k_cvth<<<dim3(C_DIM / 256, MLP_DIM), blk>>>(W_mo, Wmo2t, MLP_DIM, C_DIM, C_DIM);
    tgemm_h<float, true, 0><<<dim3(C_DIM / 128, MB), blk, GSMEM>>>(
        mlps, MLP_DIM, Wmo2t, C_DIM, b_mo, x2, C_DIM, out, C_DIM, MLP_DIM);
}